// round 1
// baseline (speedup 1.0000x reference)
#include <cuda_runtime.h>
#include <math.h>

// B=64, T=20, N=100, F=64, H=256
#define Bz 64
#define Tz 20
#define Nz 100
#define Fz 64
#define Hz 256
#define ELEMS (64UL*20UL*100UL*256UL)   // 32,768,000

// Scratch buffers (static device globals: allowed; no runtime allocation)
__device__ float g_h[ELEMS];
__device__ float g_g[ELEMS];
__device__ float g_q[ELEMS];
__device__ float g_k[ELEMS];
__device__ float g_v[ELEMS];

// ---------------------------------------------------------------------------
// adjmul: out[bt,n,f] = sum_m adj[n,m] * h[bt,m,f]
// One block per (b,t). adj (100x100) + full h slab (100xF) live in smem.
// ---------------------------------------------------------------------------
__global__ void adjmul_kernel(const float* __restrict__ h,
                              const float* __restrict__ adj,
                              float* __restrict__ out, int F) {
    extern __shared__ float sm[];
    float* adj_s = sm;             // 100*100
    float* h_s   = sm + 10000;     // 100*F
    const int bt = blockIdx.x;
    const float* hp = h + (size_t)bt * Nz * F;
    float* op = out + (size_t)bt * Nz * F;

    for (int i = threadIdx.x; i < 10000; i += blockDim.x) adj_s[i] = adj[i];
    for (int i = threadIdx.x; i < Nz * F; i += blockDim.x) h_s[i] = hp[i];
    __syncthreads();

    const int nf2 = F >> 1;                 // float2 lanes over f
    const int fp = threadIdx.x & (nf2 - 1); // f-pair index
    const int nl = threadIdx.x / nf2;       // n lane
    const int nlanes = blockDim.x / nf2;
    const float2* h2 = (const float2*)h_s;
    float2* o2 = (float2*)op;

    for (int n0 = nl * 4; n0 < Nz; n0 += nlanes * 4) {
        float2 a0c = make_float2(0.f, 0.f), a1c = a0c, a2c = a0c, a3c = a0c;
        #pragma unroll 4
        for (int m = 0; m < Nz; m++) {
            float2 hv = h2[m * nf2 + fp];
            float w0 = adj_s[(n0 + 0) * Nz + m];
            float w1 = adj_s[(n0 + 1) * Nz + m];
            float w2 = adj_s[(n0 + 2) * Nz + m];
            float w3 = adj_s[(n0 + 3) * Nz + m];
            a0c.x += w0 * hv.x; a0c.y += w0 * hv.y;
            a1c.x += w1 * hv.x; a1c.y += w1 * hv.y;
            a2c.x += w2 * hv.x; a2c.y += w2 * hv.y;
            a3c.x += w3 * hv.x; a3c.y += w3 * hv.y;
        }
        o2[(n0 + 0) * nf2 + fp] = a0c;
        o2[(n0 + 1) * nf2 + fp] = a1c;
        o2[(n0 + 2) * nf2 + fp] = a2c;
        o2[(n0 + 3) * nf2 + fp] = a3c;
    }
}

// ---------------------------------------------------------------------------
// GEMM: out[M,256] = op(A[M,K] @ W[K,256] + bias) (+ res), op = optional relu
// BM=128, BN=64, BK=16, 256 threads, 8x4 register tile per thread.
// ---------------------------------------------------------------------------
#define GBM 128
#define GBN 64
#define GBK 16
#define GAP 132   // A_s pitch (transposed: [k][m])
#define GBP 68    // B_s pitch

__global__ __launch_bounds__(256)
void gemm_kernel(const float* __restrict__ A, const float* __restrict__ W,
                 const float* __restrict__ bias, const float* __restrict__ res,
                 float* __restrict__ out, int K, int do_relu) {
    __shared__ float A_s[GBK * GAP];
    __shared__ float B_s[GBK * GBP];

    const int m0 = blockIdx.x * GBM;
    const int n0 = blockIdx.y * GBN;
    const int tid = threadIdx.x;
    const int tm = tid >> 4;   // 0..15 -> 8 rows each
    const int tn = tid & 15;   // 0..15 -> 4 cols each

    float acc[8][4];
    #pragma unroll
    for (int i = 0; i < 8; i++)
        #pragma unroll
        for (int j = 0; j < 4; j++) acc[i][j] = 0.f;

    const int bk_ = tid >> 4;  // 0..15 (k row for B load)
    const int bnq = tid & 15;  // 0..15 (float4 col for B load)

    for (int k0 = 0; k0 < K; k0 += GBK) {
        // A tile: 128 rows x 16 k = 512 float4 loads; transpose into A_s[k][m]
        #pragma unroll
        for (int l = 0; l < 2; l++) {
            int idx = tid + l * 256;
            int row = idx >> 2;
            int kq = idx & 3;
            float4 av = *(const float4*)&A[(size_t)(m0 + row) * K + k0 + kq * 4];
            A_s[(kq * 4 + 0) * GAP + row] = av.x;
            A_s[(kq * 4 + 1) * GAP + row] = av.y;
            A_s[(kq * 4 + 2) * GAP + row] = av.z;
            A_s[(kq * 4 + 3) * GAP + row] = av.w;
        }
        // B tile: 16 k x 64 n
        {
            float4 bv = *(const float4*)&W[(size_t)(k0 + bk_) * 256 + n0 + bnq * 4];
            *(float4*)&B_s[bk_ * GBP + bnq * 4] = bv;
        }
        __syncthreads();

        #pragma unroll
        for (int k = 0; k < GBK; k++) {
            float4 av0 = *(const float4*)&A_s[k * GAP + tm * 8];
            float4 av1 = *(const float4*)&A_s[k * GAP + tm * 8 + 4];
            float4 bv  = *(const float4*)&B_s[k * GBP + tn * 4];
            float a[8] = {av0.x, av0.y, av0.z, av0.w, av1.x, av1.y, av1.z, av1.w};
            float bb[4] = {bv.x, bv.y, bv.z, bv.w};
            #pragma unroll
            for (int i = 0; i < 8; i++)
                #pragma unroll
                for (int j = 0; j < 4; j++)
                    acc[i][j] += a[i] * bb[j];
        }
        __syncthreads();
    }

    float4 biasv = *(const float4*)&bias[n0 + tn * 4];
    float bb[4] = {biasv.x, biasv.y, biasv.z, biasv.w};
    #pragma unroll
    for (int i = 0; i < 8; i++) {
        size_t orow = (size_t)(m0 + tm * 8 + i) * 256 + n0 + tn * 4;
        float4 r;
        r.x = acc[i][0] + bb[0];
        r.y = acc[i][1] + bb[1];
        r.z = acc[i][2] + bb[2];
        r.w = acc[i][3] + bb[3];
        if (do_relu) {
            r.x = fmaxf(r.x, 0.f); r.y = fmaxf(r.y, 0.f);
            r.z = fmaxf(r.z, 0.f); r.w = fmaxf(r.w, 0.f);
        }
        if (res) {
            float4 rv = *(const float4*)&res[orow];
            r.x += rv.x; r.y += rv.y; r.z += rv.z; r.w += rv.w;
        }
        *(float4*)&out[orow] = r;
    }
}

// ---------------------------------------------------------------------------
// Temporal attention, one block per (b,n). T=20, H=256.
// scores[t,s] = q[t]·k[s] / 16; softmax over s; out[t] = sum_s p[t,s] v[s]
// ---------------------------------------------------------------------------
#define QS 257  // smem row stride (odd -> conflict-free dot products)

__global__ __launch_bounds__(512)
void attn_kernel(const float* __restrict__ q, const float* __restrict__ k,
                 const float* __restrict__ v, float* __restrict__ out) {
    extern __shared__ float sm[];
    float* q_s = sm;               // 20*257
    float* k_s = q_s + Tz * QS;
    float* v_s = k_s + Tz * QS;
    float* p_s = v_s + Tz * QS;    // 20*21

    const int b = blockIdx.x / Nz;
    const int n = blockIdx.x % Nz;
    const size_t base = ((size_t)b * Tz * Nz + n) * Hz;
    const size_t tstride = (size_t)Nz * Hz;

    for (int i = threadIdx.x; i < Tz * Hz; i += blockDim.x) {
        int t = i >> 8; int hh = i & 255;
        q_s[t * QS + hh] = q[base + t * tstride + hh];
        k_s[t * QS + hh] = k[base + t * tstride + hh];
        v_s[t * QS + hh] = v[base + t * tstride + hh];
    }
    __syncthreads();

    if (threadIdx.x < Tz * Tz) {
        int t = threadIdx.x / Tz, s = threadIdx.x % Tz;
        float acc = 0.f;
        #pragma unroll 8
        for (int c = 0; c < Hz; c++) acc += q_s[t * QS + c] * k_s[s * QS + c];
        p_s[t * 21 + s] = acc * 0.0625f;   // 1/sqrt(256)
    }
    __syncthreads();

    if (threadIdx.x < Tz) {
        int t = threadIdx.x;
        float mx = -1e30f;
        #pragma unroll
        for (int s = 0; s < Tz; s++) mx = fmaxf(mx, p_s[t * 21 + s]);
        float sum = 0.f;
        #pragma unroll
        for (int s = 0; s < Tz; s++) {
            float e = expf(p_s[t * 21 + s] - mx);
            p_s[t * 21 + s] = e; sum += e;
        }
        float inv = 1.f / sum;
        #pragma unroll
        for (int s = 0; s < Tz; s++) p_s[t * 21 + s] *= inv;
    }
    __syncthreads();

    // 512 threads: hh = tid%256, each handles 10 t's
    const int hh = threadIdx.x & 255;
    const int th = threadIdx.x >> 8;          // 0 or 1
    for (int t = th * 10; t < th * 10 + 10; t++) {
        float acc = 0.f;
        #pragma unroll
        for (int s = 0; s < Tz; s++) acc += p_s[t * 21 + s] * v_s[s * QS + hh];
        out[base + t * tstride + hh] = acc;
    }
}

// ---------------------------------------------------------------------------
// LayerNorm over H=256 per row. One block (256 thr) per row.
// ---------------------------------------------------------------------------
__global__ __launch_bounds__(256)
void ln_kernel(const float* __restrict__ a, const float* __restrict__ gamma,
               const float* __restrict__ beta, float* __restrict__ out) {
    __shared__ float ss[8], qq[8];
    const size_t row = blockIdx.x;
    const int t = threadIdx.x;
    float x = a[row * 256 + t];
    float s = x, q = x * x;
    #pragma unroll
    for (int o = 16; o > 0; o >>= 1) {
        s += __shfl_xor_sync(0xffffffffu, s, o);
        q += __shfl_xor_sync(0xffffffffu, q, o);
    }
    int w = t >> 5, l = t & 31;
    if (l == 0) { ss[w] = s; qq[w] = q; }
    __syncthreads();
    float S = 0.f, Q = 0.f;
    #pragma unroll
    for (int i = 0; i < 8; i++) { S += ss[i]; Q += qq[i]; }
    float mu = S * (1.f / 256.f);
    float var = Q * (1.f / 256.f) - mu * mu;
    float r = rsqrtf(var + 1e-5f);
    out[row * 256 + t] = (x - mu) * r * gamma[t] + beta[t];
}

// ---------------------------------------------------------------------------
// launch
// ---------------------------------------------------------------------------
extern "C" void kernel_launch(void* const* d_in, const int* in_sizes, int n_in,
                              void* d_out, int out_size) {
    const float* x    = (const float*)d_in[0];
    const float* adj  = (const float*)d_in[1];
    const float* W0   = (const float*)d_in[2];
    const float* b0   = (const float*)d_in[3];
    const float* W1   = (const float*)d_in[4];
    const float* b1   = (const float*)d_in[5];
    const float* W2   = (const float*)d_in[6];
    const float* b2   = (const float*)d_in[7];
    const float* Wq   = (const float*)d_in[8];
    const float* bq   = (const float*)d_in[9];
    const float* Wk   = (const float*)d_in[10];
    const float* bk   = (const float*)d_in[11];
    const float* Wv   = (const float*)d_in[12];
    const float* bv   = (const float*)d_in[13];
    const float* Wp   = (const float*)d_in[14];
    const float* bp   = (const float*)d_in[15];
    const float* gamma = (const float*)d_in[16];
    const float* beta  = (const float*)d_in[17];
    float* out = (float*)d_out;

    float *ph, *pg, *pq, *pk, *pv;
    cudaGetSymbolAddress((void**)&ph, g_h);
    cudaGetSymbolAddress((void**)&pg, g_g);
    cudaGetSymbolAddress((void**)&pq, g_q);
    cudaGetSymbolAddress((void**)&pk, g_k);
    cudaGetSymbolAddress((void**)&pv, g_v);

    const int smem_adj256 = (10000 + Nz * Hz) * 4;         // 142.4 KB
    const int smem_adj64  = (10000 + Nz * Fz) * 4;         // 65.6 KB
    const int smem_attn   = (3 * Tz * QS + Tz * 21) * 4;   // 63.4 KB
    cudaFuncSetAttribute(adjmul_kernel, cudaFuncAttributeMaxDynamicSharedMemorySize, smem_adj256);
    cudaFuncSetAttribute(attn_kernel,   cudaFuncAttributeMaxDynamicSharedMemorySize, smem_attn);

    const int BT = Bz * Tz;                 // 1280
    const int M = Bz * Tz * Nz;             // 128000
    dim3 gg(M / GBM, 256 / GBN);            // (1000, 4)

    // GCN layer 0 (F=64 -> H=256, no residual)
    adjmul_kernel<<<BT, 256, smem_adj64>>>(x, adj, pg, Fz);
    gemm_kernel<<<gg, 256>>>(pg, W0, b0, nullptr, ph, Fz, 1);
    // GCN layer 1 (residual, in-place add into ph)
    adjmul_kernel<<<BT, 256, smem_adj256>>>(ph, adj, pg, Hz);
    gemm_kernel<<<gg, 256>>>(pg, W1, b1, ph, ph, Hz, 1);
    // GCN layer 2
    adjmul_kernel<<<BT, 256, smem_adj256>>>(ph, adj, pg, Hz);
    gemm_kernel<<<gg, 256>>>(pg, W2, b2, ph, ph, Hz, 1);
    // Q, K, V projections
    gemm_kernel<<<gg, 256>>>(ph, Wq, bq, nullptr, pq, Hz, 0);
    gemm_kernel<<<gg, 256>>>(ph, Wk, bk, nullptr, pk, Hz, 0);
    gemm_kernel<<<gg, 256>>>(ph, Wv, bv, nullptr, pv, Hz, 0);
    // Temporal attention
    attn_kernel<<<Bz * Nz, 512, smem_attn>>>(pq, pk, pv, pg);
    // Output projection
    gemm_kernel<<<gg, 256>>>(pg, Wp, bp, nullptr, pq, Hz, 0);
    // LayerNorm -> final output
    ln_kernel<<<M, 256>>>(pq, gamma, beta, out);
}

// round 5
// speedup vs baseline: 1.3876x; 1.3876x over previous
#include <cuda_runtime.h>
#include <cuda_fp16.h>
#include <math.h>
#include <stdint.h>

// B=64, T=20, N=100, F=64, H=256
#define Bz 64
#define Tz 20
#define Nz 100
#define Fz 64
#define Hz 256
#define ELEMS (64UL*20UL*100UL*256UL)   // 32,768,000

// Scratch buffers
__device__ float g_h[ELEMS];
__device__ float g_g[ELEMS];
__device__ float g_q[ELEMS];
__device__ float g_k[ELEMS];
__device__ float g_v[ELEMS];
// Packed weights: 7 matrices, each up to 2 nblk x 4 kchunk x (hi 16KB + lo 16KB)
#define WPACK_STRIDE 262144
__device__ uint8_t g_wpack[7 * WPACK_STRIDE];

// ---------------------------------------------------------------------------
// helpers
// ---------------------------------------------------------------------------
__device__ __forceinline__ uint32_t smem_u32(const void* p) {
    uint32_t a;
    asm("{ .reg .u64 t; cvta.to.shared.u64 t, %1; cvt.u32.u64 %0, t; }" : "=r"(a) : "l"(p));
    return a;
}
__device__ __forceinline__ void ldsm_x4(uint32_t* r, uint32_t addr) {
    asm volatile("ldmatrix.sync.aligned.m8n8.x4.shared.b16 {%0,%1,%2,%3}, [%4];"
                 : "=r"(r[0]), "=r"(r[1]), "=r"(r[2]), "=r"(r[3]) : "r"(addr));
}
__device__ __forceinline__ void ldsm_x2(uint32_t* r, uint32_t addr) {
    asm volatile("ldmatrix.sync.aligned.m8n8.x2.shared.b16 {%0,%1}, [%2];"
                 : "=r"(r[0]), "=r"(r[1]) : "r"(addr));
}
__device__ __forceinline__ void mma16816(float* d, const uint32_t* a, const uint32_t* b) {
    asm volatile(
        "mma.sync.aligned.m16n8k16.row.col.f32.f16.f16.f32 "
        "{%0,%1,%2,%3}, {%4,%5,%6,%7}, {%8,%9}, {%0,%1,%2,%3};"
        : "+f"(d[0]), "+f"(d[1]), "+f"(d[2]), "+f"(d[3])
        : "r"(a[0]), "r"(a[1]), "r"(a[2]), "r"(a[3]), "r"(b[0]), "r"(b[1]));
}

// ---------------------------------------------------------------------------
// Weight pack: W[K,256] -> per (nblk of 128 cols, kchunk of 64) swizzled fp16
// hi/lo tiles, exact smem image: row = n_local (128B), 16B-chunk swizzle
// byte_off(n,k) = n*128 + (((k>>3) ^ (n&7))<<4) + (k&7)*2
// ---------------------------------------------------------------------------
__global__ void pack_w_kernel(const float* __restrict__ W, int K, uint8_t* __restrict__ dst) {
    int i = blockIdx.x * blockDim.x + threadIdx.x;
    if (i >= K * 256) return;
    int k = i >> 8, n = i & 255;
    float v = W[i];
    __half h = __float2half(v);
    __half l = __float2half(v - __half2float(h));
    int nblk = n >> 7, rn = n & 127, chunk = k >> 6, kl = k & 63;
    int ncK = K >> 6;
    uint32_t boff = (uint32_t)(rn * 128 + ((((kl >> 3) ^ (rn & 7))) << 4) + (kl & 7) * 2);
    uint8_t* tile = dst + (size_t)(nblk * ncK + chunk) * 32768;
    *(__half*)(tile + boff) = h;
    *(__half*)(tile + 16384 + boff) = l;
}

// ---------------------------------------------------------------------------
// Warp-MMA fp16x3 GEMM: out[M,256] = op(A[M,K] @ W + bias) (+res)
// CTA 128x128, 8 warps (2m x 4n), warp tile 64x32, K chunked by 64.
// ---------------------------------------------------------------------------
#define GOFF_BIAS 0
#define GOFF_AHI 512
#define GOFF_ALO (GOFF_AHI + 16384)
#define GOFF_BHI (GOFF_ALO + 16384)
#define GOFF_BLO (GOFF_BHI + 16384)
#define SMEM_GEMM (GOFF_BLO + 16384)

__global__ __launch_bounds__(256)
void mma_gemm(const float* __restrict__ A, const uint8_t* __restrict__ Wp,
              const float* __restrict__ bias, const float* res,
              float* out, int K, int do_relu) {
    extern __shared__ char sm[];
    const uint32_t sbase = smem_u32(sm);
    const int tid = threadIdx.x;
    const int warp = tid >> 5, lane = tid & 31;
    const int m0 = blockIdx.x * 128;
    const int nblk = blockIdx.y;
    const int n0 = nblk * 128;
    const int nc = K >> 6;

    if (tid < 128) ((float*)sm)[tid] = bias[n0 + tid];

    float acc[4][4][4] = {};
    const int wm = warp >> 2, wn = warp & 3;
    const int m_base = wm * 64, n_base = wn * 32;

    // ldmatrix per-lane addressing components
    const int amat = lane >> 3, ar = lane & 7;
    const int arow_b = m_base + (amat & 1) * 8 + ar;   // + mt*16
    const int asel = amat >> 1;                        // 0/1 -> +8 in k
    const int l16 = lane & 15;
    const int bmat = l16 >> 3, br = l16 & 7;

    for (int c = 0; c < nc; c++) {
        const int k0 = c * 64;
        // --- stage A chunk: 128 rows x 64 k, fp32 -> fp16 hi/lo, swizzled ---
        #pragma unroll
        for (int i = 0; i < 4; i++) {
            int chunk = tid + i * 256;          // 1024 16B-chunks
            int row = chunk >> 3, kc = chunk & 7;
            const float4* src = (const float4*)&A[(size_t)(m0 + row) * K + k0 + kc * 8];
            float4 v0 = src[0], v1 = src[1];
            float vv[8] = {v0.x, v0.y, v0.z, v0.w, v1.x, v1.y, v1.z, v1.w};
            uint32_t hi[4], lo[4];
            #pragma unroll
            for (int j = 0; j < 4; j++) {
                __half h0 = __float2half(vv[2 * j]);
                __half h1 = __float2half(vv[2 * j + 1]);
                __half l0 = __float2half(vv[2 * j] - __half2float(h0));
                __half l1 = __float2half(vv[2 * j + 1] - __half2float(h1));
                __half2 hp = make_half2(h0, h1);
                __half2 lp = make_half2(l0, l1);
                hi[j] = *(uint32_t*)&hp;
                lo[j] = *(uint32_t*)&lp;
            }
            uint32_t boff = (uint32_t)(row * 128 + ((kc ^ (row & 7)) << 4));
            *(uint4*)(sm + GOFF_AHI + boff) = make_uint4(hi[0], hi[1], hi[2], hi[3]);
            *(uint4*)(sm + GOFF_ALO + boff) = make_uint4(lo[0], lo[1], lo[2], lo[3]);
        }
        // --- stage B chunk: identity copy of prepacked 32KB (hi||lo) ---
        {
            const float4* srcH = (const float4*)(Wp + (size_t)(nblk * nc + c) * 32768);
            float4* dH = (float4*)(sm + GOFF_BHI);
            #pragma unroll
            for (int i = 0; i < 8; i++) dH[tid + i * 256] = srcH[tid + i * 256];
        }
        __syncthreads();

        #pragma unroll
        for (int ks = 0; ks < 4; ks++) {
            uint32_t bh[4][2], bl[4][2];
            #pragma unroll
            for (int nt = 0; nt < 4; nt++) {
                int brow = n_base + nt * 8 + br;
                uint32_t boffs = (uint32_t)(brow * 128 + (((ks * 2 + bmat) ^ (brow & 7)) << 4));
                ldsm_x2(bh[nt], sbase + GOFF_BHI + boffs);
                ldsm_x2(bl[nt], sbase + GOFF_BLO + boffs);
            }
            #pragma unroll
            for (int mt = 0; mt < 4; mt++) {
                int arow = arow_b + mt * 16;
                uint32_t aoffs = (uint32_t)(arow * 128 + (((ks * 2 + asel) ^ (arow & 7)) << 4));
                uint32_t ah[4], al[4];
                ldsm_x4(ah, sbase + GOFF_AHI + aoffs);
                ldsm_x4(al, sbase + GOFF_ALO + aoffs);
                #pragma unroll
                for (int nt = 0; nt < 4; nt++) {
                    mma16816(acc[mt][nt], ah, bh[nt]);
                    mma16816(acc[mt][nt], ah, bl[nt]);
                    mma16816(acc[mt][nt], al, bh[nt]);
                }
            }
        }
        __syncthreads();
    }

    // --- epilogue: bias + relu + residual, direct register -> gmem ---
    const float* bias_s = (const float*)sm;
    const int g = lane >> 2, tc = lane & 3;
    #pragma unroll
    for (int mt = 0; mt < 4; mt++) {
        int r0 = m0 + m_base + mt * 16 + g;
        #pragma unroll
        for (int nt = 0; nt < 4; nt++) {
            int cl = n_base + nt * 8 + tc * 2;
            float b0 = bias_s[cl], b1 = bias_s[cl + 1];
            float2 o0, o1;
            o0.x = acc[mt][nt][0] + b0; o0.y = acc[mt][nt][1] + b1;
            o1.x = acc[mt][nt][2] + b0; o1.y = acc[mt][nt][3] + b1;
            if (do_relu) {
                o0.x = fmaxf(o0.x, 0.f); o0.y = fmaxf(o0.y, 0.f);
                o1.x = fmaxf(o1.x, 0.f); o1.y = fmaxf(o1.y, 0.f);
            }
            size_t i0 = (size_t)r0 * 256 + n0 + cl;
            size_t i1 = (size_t)(r0 + 8) * 256 + n0 + cl;
            if (res) {
                float2 rv0 = *(const float2*)&res[i0];
                float2 rv1 = *(const float2*)&res[i1];
                o0.x += rv0.x; o0.y += rv0.y;
                o1.x += rv1.x; o1.y += rv1.y;
            }
            *(float2*)&out[i0] = o0;
            *(float2*)&out[i1] = o1;
        }
    }
}

// ---------------------------------------------------------------------------
// adjmul: out[bt,n,f0+f] = sum_m adj[n,m] * h[bt,m,f0+f], f in [0,F_chunk)
// blockIdx.x = bt, blockIdx.y = f-chunk index.
// ---------------------------------------------------------------------------
__global__ void adjmul_kernel(const float* __restrict__ h,
                              const float* __restrict__ adj,
                              float* __restrict__ out, int F_total, int F_chunk) {
    extern __shared__ float smf[];
    float* adj_s = smf;
    float* h_s   = smf + 10000;
    const int bt = blockIdx.x;
    const int f0 = blockIdx.y * F_chunk;
    const float* hp = h + (size_t)bt * Nz * F_total;
    float* op = out + (size_t)bt * Nz * F_total;

    for (int i = threadIdx.x; i < 10000; i += blockDim.x) adj_s[i] = adj[i];
    for (int i = threadIdx.x; i < Nz * F_chunk; i += blockDim.x) {
        int row = i / F_chunk, col = i - row * F_chunk;
        h_s[i] = hp[(size_t)row * F_total + f0 + col];
    }
    __syncthreads();

    const int nf2 = F_chunk >> 1;
    const int fp = threadIdx.x & (nf2 - 1);
    const int nl = threadIdx.x / nf2;
    const int nlanes = blockDim.x / nf2;
    const float2* h2 = (const float2*)h_s;
    float2* o2 = (float2*)op;
    const int ostride = F_total >> 1;
    const int obase = f0 >> 1;

    for (int n0 = nl * 4; n0 < Nz; n0 += nlanes * 4) {
        float2 a0c = make_float2(0.f, 0.f), a1c = a0c, a2c = a0c, a3c = a0c;
        #pragma unroll 4
        for (int m = 0; m < Nz; m++) {
            float2 hv = h2[m * nf2 + fp];
            float w0 = adj_s[(n0 + 0) * Nz + m];
            float w1 = adj_s[(n0 + 1) * Nz + m];
            float w2 = adj_s[(n0 + 2) * Nz + m];
            float w3 = adj_s[(n0 + 3) * Nz + m];
            a0c.x += w0 * hv.x; a0c.y += w0 * hv.y;
            a1c.x += w1 * hv.x; a1c.y += w1 * hv.y;
            a2c.x += w2 * hv.x; a2c.y += w2 * hv.y;
            a3c.x += w3 * hv.x; a3c.y += w3 * hv.y;
        }
        o2[(n0 + 0) * ostride + obase + fp] = a0c;
        o2[(n0 + 1) * ostride + obase + fp] = a1c;
        o2[(n0 + 2) * ostride + obase + fp] = a2c;
        o2[(n0 + 3) * ostride + obase + fp] = a3c;
    }
}

// ---------------------------------------------------------------------------
// Temporal attention
// ---------------------------------------------------------------------------
#define QS 257

__global__ __launch_bounds__(512)
void attn_kernel(const float* __restrict__ q, const float* __restrict__ k,
                 const float* __restrict__ v, float* __restrict__ out) {
    extern __shared__ float smf[];
    float* q_s = smf;
    float* k_s = q_s + Tz * QS;
    float* v_s = k_s + Tz * QS;
    float* p_s = v_s + Tz * QS;

    const int b = blockIdx.x / Nz;
    const int n = blockIdx.x % Nz;
    const size_t base = ((size_t)b * Tz * Nz + n) * Hz;
    const size_t tstride = (size_t)Nz * Hz;

    for (int i = threadIdx.x; i < Tz * Hz; i += blockDim.x) {
        int t = i >> 8; int hh = i & 255;
        q_s[t * QS + hh] = q[base + t * tstride + hh];
        k_s[t * QS + hh] = k[base + t * tstride + hh];
        v_s[t * QS + hh] = v[base + t * tstride + hh];
    }
    __syncthreads();

    if (threadIdx.x < Tz * Tz) {
        int t = threadIdx.x / Tz, s = threadIdx.x % Tz;
        float acc = 0.f;
        #pragma unroll 8
        for (int c = 0; c < Hz; c++) acc += q_s[t * QS + c] * k_s[s * QS + c];
        p_s[t * 21 + s] = acc * 0.0625f;
    }
    __syncthreads();

    if (threadIdx.x < Tz) {
        int t = threadIdx.x;
        float mx = -1e30f;
        #pragma unroll
        for (int s = 0; s < Tz; s++) mx = fmaxf(mx, p_s[t * 21 + s]);
        float sum = 0.f;
        #pragma unroll
        for (int s = 0; s < Tz; s++) {
            float e = expf(p_s[t * 21 + s] - mx);
            p_s[t * 21 + s] = e; sum += e;
        }
        float inv = 1.f / sum;
        #pragma unroll
        for (int s = 0; s < Tz; s++) p_s[t * 21 + s] *= inv;
    }
    __syncthreads();

    const int hh = threadIdx.x & 255;
    const int th = threadIdx.x >> 8;
    for (int t = th * 10; t < th * 10 + 10; t++) {
        float acc = 0.f;
        #pragma unroll
        for (int s = 0; s < Tz; s++) acc += p_s[t * 21 + s] * v_s[s * QS + hh];
        out[base + t * tstride + hh] = acc;
    }
}

// ---------------------------------------------------------------------------
// LayerNorm
// ---------------------------------------------------------------------------
__global__ __launch_bounds__(256)
void ln_kernel(const float* __restrict__ a, const float* __restrict__ gamma,
               const float* __restrict__ beta, float* __restrict__ out) {
    __shared__ float ss[8], qq[8];
    const size_t row = blockIdx.x;
    const int t = threadIdx.x;
    float x = a[row * 256 + t];
    float s = x, q = x * x;
    #pragma unroll
    for (int o = 16; o > 0; o >>= 1) {
        s += __shfl_xor_sync(0xffffffffu, s, o);
        q += __shfl_xor_sync(0xffffffffu, q, o);
    }
    int w = t >> 5, l = t & 31;
    if (l == 0) { ss[w] = s; qq[w] = q; }
    __syncthreads();
    float S = 0.f, Q = 0.f;
    #pragma unroll
    for (int i = 0; i < 8; i++) { S += ss[i]; Q += qq[i]; }
    float mu = S * (1.f / 256.f);
    float var = Q * (1.f / 256.f) - mu * mu;
    float r = rsqrtf(var + 1e-5f);
    out[row * 256 + t] = (x - mu) * r * gamma[t] + beta[t];
}

// ---------------------------------------------------------------------------
// launch
// ---------------------------------------------------------------------------
extern "C" void kernel_launch(void* const* d_in, const int* in_sizes, int n_in,
                              void* d_out, int out_size) {
    const float* x    = (const float*)d_in[0];
    const float* adj  = (const float*)d_in[1];
    const float* W0   = (const float*)d_in[2];
    const float* b0   = (const float*)d_in[3];
    const float* W1   = (const float*)d_in[4];
    const float* b1   = (const float*)d_in[5];
    const float* W2   = (const float*)d_in[6];
    const float* b2   = (const float*)d_in[7];
    const float* Wq   = (const float*)d_in[8];
    const float* bq   = (const float*)d_in[9];
    const float* Wk   = (const float*)d_in[10];
    const float* bk   = (const float*)d_in[11];
    const float* Wv   = (const float*)d_in[12];
    const float* bv   = (const float*)d_in[13];
    const float* Wp   = (const float*)d_in[14];
    const float* bp   = (const float*)d_in[15];
    const float* gamma = (const float*)d_in[16];
    const float* beta  = (const float*)d_in[17];
    float* out = (float*)d_out;

    float *ph, *pg, *pq, *pk, *pv;
    uint8_t* wp;
    cudaGetSymbolAddress((void**)&ph, g_h);
    cudaGetSymbolAddress((void**)&pg, g_g);
    cudaGetSymbolAddress((void**)&pq, g_q);
    cudaGetSymbolAddress((void**)&pk, g_k);
    cudaGetSymbolAddress((void**)&pv, g_v);
    cudaGetSymbolAddress((void**)&wp, g_wpack);

    const int smem_adj64  = (10000 + Nz * Fz) * 4;       // 65.6 KB
    const int smem_adj128 = (10000 + Nz * 128) * 4;      // 91.2 KB
    const int smem_attn   = (3 * Tz * QS + Tz * 21) * 4; // 63.4 KB
    cudaFuncSetAttribute(adjmul_kernel, cudaFuncAttributeMaxDynamicSharedMemorySize, smem_adj128);
    cudaFuncSetAttribute(attn_kernel,   cudaFuncAttributeMaxDynamicSharedMemorySize, smem_attn);
    cudaFuncSetAttribute(mma_gemm,      cudaFuncAttributeMaxDynamicSharedMemorySize, SMEM_GEMM);

    // pack weights (fp16 hi/lo, swizzled ldmatrix layout)
    pack_w_kernel<<<(64 * 256 + 255) / 256, 256>>>(W0, 64, wp + 0 * WPACK_STRIDE);
    pack_w_kernel<<<(256 * 256 + 255) / 256, 256>>>(W1, 256, wp + 1 * WPACK_STRIDE);
    pack_w_kernel<<<(256 * 256 + 255) / 256, 256>>>(W2, 256, wp + 2 * WPACK_STRIDE);
    pack_w_kernel<<<(256 * 256 + 255) / 256, 256>>>(Wq, 256, wp + 3 * WPACK_STRIDE);
    pack_w_kernel<<<(256 * 256 + 255) / 256, 256>>>(Wk, 256, wp + 4 * WPACK_STRIDE);
    pack_w_kernel<<<(256 * 256 + 255) / 256, 256>>>(Wv, 256, wp + 5 * WPACK_STRIDE);
    pack_w_kernel<<<(256 * 256 + 255) / 256, 256>>>(Wp, 256, wp + 6 * WPACK_STRIDE);

    const int BT = Bz * Tz;                 // 1280
    const int M = Bz * Tz * Nz;             // 128000
    dim3 gg(M / 128, 2);

    // GCN layer 0 (F=64 -> H=256)
    adjmul_kernel<<<dim3(BT, 1), 256, smem_adj64>>>(x, adj, pg, Fz, Fz);
    mma_gemm<<<gg, 256, SMEM_GEMM>>>(pg, wp + 0 * WPACK_STRIDE, b0, nullptr, ph, Fz, 1);
    // GCN layer 1 (residual)
    adjmul_kernel<<<dim3(BT, 2), 256, smem_adj128>>>(ph, adj, pg, Hz, 128);
    mma_gemm<<<gg, 256, SMEM_GEMM>>>(pg, wp + 1 * WPACK_STRIDE, b1, ph, ph, Hz, 1);
    // GCN layer 2 (residual)
    adjmul_kernel<<<dim3(BT, 2), 256, smem_adj128>>>(ph, adj, pg, Hz, 128);
    mma_gemm<<<gg, 256, SMEM_GEMM>>>(pg, wp + 2 * WPACK_STRIDE, b2, ph, ph, Hz, 1);
    // Q, K, V
    mma_gemm<<<gg, 256, SMEM_GEMM>>>(ph, wp + 3 * WPACK_STRIDE, bq, nullptr, pq, Hz, 0);
    mma_gemm<<<gg, 256, SMEM_GEMM>>>(ph, wp + 4 * WPACK_STRIDE, bk, nullptr, pk, Hz, 0);
    mma_gemm<<<gg, 256, SMEM_GEMM>>>(ph, wp + 5 * WPACK_STRIDE, bv, nullptr, pv, Hz, 0);
    // attention
    attn_kernel<<<Bz * Nz, 512, smem_attn>>>(pq, pk, pv, pg);
    // output projection
    mma_gemm<<<gg, 256, SMEM_GEMM>>>(pg, wp + 6 * WPACK_STRIDE, bp, nullptr, pq, Hz, 0);
    // layernorm
    ln_kernel<<<M, 256>>>(pq, gamma, beta, out);
}

// round 7
// speedup vs baseline: 1.6132x; 1.1626x over previous
#include <cuda_runtime.h>
#include <cuda_fp16.h>
#include <math.h>
#include <stdint.h>

// B=64, T=20, N=100, F=64, H=256
#define Bz 64
#define Tz 20
#define Nz 100
#define Fz 64
#define Hz 256
#define ELEMS (64UL*20UL*100UL*256UL)   // 32,768,000

__device__ float g_h[ELEMS];
__device__ float g_g[ELEMS];
__device__ float g_q[ELEMS];
__device__ float g_k[ELEMS];
__device__ float g_v[ELEMS];
#define WPACK_STRIDE 262144
__device__ uint8_t g_wpack[7 * WPACK_STRIDE];

// ---------------------------------------------------------------------------
// helpers
// ---------------------------------------------------------------------------
__device__ __forceinline__ uint32_t smem_u32(const void* p) {
    uint32_t a;
    asm("{ .reg .u64 t; cvta.to.shared.u64 t, %1; cvt.u32.u64 %0, t; }" : "=r"(a) : "l"(p));
    return a;
}
__device__ __forceinline__ void ldsm_x4(uint32_t* r, uint32_t addr) {
    asm volatile("ldmatrix.sync.aligned.m8n8.x4.shared.b16 {%0,%1,%2,%3}, [%4];"
                 : "=r"(r[0]), "=r"(r[1]), "=r"(r[2]), "=r"(r[3]) : "r"(addr));
}
__device__ __forceinline__ void ldsm_x2(uint32_t* r, uint32_t addr) {
    asm volatile("ldmatrix.sync.aligned.m8n8.x2.shared.b16 {%0,%1}, [%2];"
                 : "=r"(r[0]), "=r"(r[1]) : "r"(addr));
}
__device__ __forceinline__ void mma16816(float* d, const uint32_t* a, const uint32_t* b) {
    asm volatile(
        "mma.sync.aligned.m16n8k16.row.col.f32.f16.f16.f32 "
        "{%0,%1,%2,%3}, {%4,%5,%6,%7}, {%8,%9}, {%0,%1,%2,%3};"
        : "+f"(d[0]), "+f"(d[1]), "+f"(d[2]), "+f"(d[3])
        : "r"(a[0]), "r"(a[1]), "r"(a[2]), "r"(a[3]), "r"(b[0]), "r"(b[1]));
}
__device__ __forceinline__ void split_h2(float x, float y, uint32_t& hi, uint32_t& lo) {
    __half h0 = __float2half(x), h1 = __float2half(y);
    __half l0 = __float2half(x - __half2float(h0));
    __half l1 = __float2half(y - __half2float(h1));
    __half2 hp = make_half2(h0, h1), lp = make_half2(l0, l1);
    hi = *(uint32_t*)&hp; lo = *(uint32_t*)&lp;
}

// ---------------------------------------------------------------------------
// Packing: all 7 weight matrices in one launch
// ---------------------------------------------------------------------------
struct W7 { const float* w[7]; };

__global__ void pack_w_all(W7 ws, uint8_t* __restrict__ dst) {
    int mat = blockIdx.y;
    int K = (mat == 0) ? 64 : 256;
    int i = blockIdx.x * blockDim.x + threadIdx.x;
    if (i >= K * 256) return;
    int k = i >> 8, n = i & 255;
    float v = ws.w[mat][i];
    __half h = __float2half(v);
    __half l = __float2half(v - __half2float(h));
    int nblk = n >> 7, rn = n & 127, chunk = k >> 6, kl = k & 63;
    int ncK = K >> 6;
    uint32_t boff = (uint32_t)(rn * 128 + ((((kl >> 3) ^ (rn & 7))) << 4) + (kl & 7) * 2);
    uint8_t* tile = dst + (size_t)mat * WPACK_STRIDE + (size_t)(nblk * ncK + chunk) * 32768;
    *(__half*)(tile + boff) = h;
    *(__half*)(tile + 16384 + boff) = l;
}

// ---------------------------------------------------------------------------
// Warp-MMA fp16x3 GEMM core: out[M,256] = op(A[M,K] @ W + bias) (+res)
// CTA 128x128, 8 warps (2m x 4n), warp tile 64x32, K chunked by 64.
// ---------------------------------------------------------------------------
#define GOFF_BIAS 0
#define GOFF_AHI 512
#define GOFF_ALO (GOFF_AHI + 16384)
#define GOFF_BHI (GOFF_ALO + 16384)
#define GOFF_BLO (GOFF_BHI + 16384)
#define SMEM_GEMM (GOFF_BLO + 16384)

__device__ __forceinline__ void gemm_core(
    const float* __restrict__ A, const uint8_t* __restrict__ Wp,
    const float* __restrict__ bias, const float* res,
    float* out, int K, int do_relu, int m0, int nblk)
{
    extern __shared__ char sm[];
    const uint32_t sbase = smem_u32(sm);
    const int tid = threadIdx.x;
    const int warp = tid >> 5, lane = tid & 31;
    const int n0 = nblk * 128;
    const int nc = K >> 6;

    if (tid < 128) ((float*)sm)[tid] = bias[n0 + tid];

    float acc[4][4][4] = {};
    const int wm = warp >> 2, wn = warp & 3;
    const int m_base = wm * 64, n_base = wn * 32;

    const int amat = lane >> 3, ar = lane & 7;
    const int arow_b = m_base + (amat & 1) * 8 + ar;
    const int asel = amat >> 1;
    const int l16 = lane & 15;
    const int bmat = l16 >> 3, br = l16 & 7;

    for (int c = 0; c < nc; c++) {
        const int k0 = c * 64;
        #pragma unroll
        for (int i = 0; i < 4; i++) {
            int chunk = tid + i * 256;
            int row = chunk >> 3, kc = chunk & 7;
            const float4* src = (const float4*)&A[(size_t)(m0 + row) * K + k0 + kc * 8];
            float4 v0 = src[0], v1 = src[1];
            uint32_t hi[4], lo[4];
            split_h2(v0.x, v0.y, hi[0], lo[0]);
            split_h2(v0.z, v0.w, hi[1], lo[1]);
            split_h2(v1.x, v1.y, hi[2], lo[2]);
            split_h2(v1.z, v1.w, hi[3], lo[3]);
            uint32_t boff = (uint32_t)(row * 128 + ((kc ^ (row & 7)) << 4));
            *(uint4*)(sm + GOFF_AHI + boff) = make_uint4(hi[0], hi[1], hi[2], hi[3]);
            *(uint4*)(sm + GOFF_ALO + boff) = make_uint4(lo[0], lo[1], lo[2], lo[3]);
        }
        {
            const float4* srcH = (const float4*)(Wp + (size_t)(nblk * nc + c) * 32768);
            float4* dH = (float4*)(sm + GOFF_BHI);
            #pragma unroll
            for (int i = 0; i < 8; i++) dH[tid + i * 256] = srcH[tid + i * 256];
        }
        __syncthreads();

        #pragma unroll
        for (int ks = 0; ks < 4; ks++) {
            uint32_t bh[4][2], bl[4][2];
            #pragma unroll
            for (int nt = 0; nt < 4; nt++) {
                int brow = n_base + nt * 8 + br;
                uint32_t boffs = (uint32_t)(brow * 128 + (((ks * 2 + bmat) ^ (brow & 7)) << 4));
                ldsm_x2(bh[nt], sbase + GOFF_BHI + boffs);
                ldsm_x2(bl[nt], sbase + GOFF_BLO + boffs);
            }
            #pragma unroll
            for (int mt = 0; mt < 4; mt++) {
                int arow = arow_b + mt * 16;
                uint32_t aoffs = (uint32_t)(arow * 128 + (((ks * 2 + asel) ^ (arow & 7)) << 4));
                uint32_t ah[4], al[4];
                ldsm_x4(ah, sbase + GOFF_AHI + aoffs);
                ldsm_x4(al, sbase + GOFF_ALO + aoffs);
                #pragma unroll
                for (int nt = 0; nt < 4; nt++) {
                    mma16816(acc[mt][nt], ah, bh[nt]);
                    mma16816(acc[mt][nt], ah, bl[nt]);
                    mma16816(acc[mt][nt], al, bh[nt]);
                }
            }
        }
        __syncthreads();
    }

    const float* bias_s = (const float*)sm;
    const int g = lane >> 2, tc = lane & 3;
    #pragma unroll
    for (int mt = 0; mt < 4; mt++) {
        int r0 = m0 + m_base + mt * 16 + g;
        #pragma unroll
        for (int nt = 0; nt < 4; nt++) {
            int cl = n_base + nt * 8 + tc * 2;
            float b0 = bias_s[cl], b1 = bias_s[cl + 1];
            float2 o0, o1;
            o0.x = acc[mt][nt][0] + b0; o0.y = acc[mt][nt][1] + b1;
            o1.x = acc[mt][nt][2] + b0; o1.y = acc[mt][nt][3] + b1;
            if (do_relu) {
                o0.x = fmaxf(o0.x, 0.f); o0.y = fmaxf(o0.y, 0.f);
                o1.x = fmaxf(o1.x, 0.f); o1.y = fmaxf(o1.y, 0.f);
            }
            size_t i0 = (size_t)r0 * 256 + n0 + cl;
            size_t i1 = (size_t)(r0 + 8) * 256 + n0 + cl;
            if (res) {
                float2 rv0 = *(const float2*)&res[i0];
                float2 rv1 = *(const float2*)&res[i1];
                o0.x += rv0.x; o0.y += rv0.y;
                o1.x += rv1.x; o1.y += rv1.y;
            }
            *(float2*)&out[i0] = o0;
            *(float2*)&out[i1] = o1;
        }
    }
}

__global__ __launch_bounds__(256)
void mma_gemm(const float* __restrict__ A, const uint8_t* __restrict__ Wp,
              const float* __restrict__ bias, const float* res,
              float* out, int K, int do_relu) {
    gemm_core(A, Wp, bias, res, out, K, do_relu, blockIdx.x * 128, blockIdx.y);
}

__global__ __launch_bounds__(256)
void qkv_gemm(const float* __restrict__ A, const uint8_t* __restrict__ WpBase,
              const float* __restrict__ bq, const float* __restrict__ bk,
              const float* __restrict__ bv,
              float* oq, float* ok, float* ov) {
    int mat = blockIdx.y >> 1, nblk = blockIdx.y & 1;
    const uint8_t* Wp = WpBase + (size_t)(3 + mat) * WPACK_STRIDE;
    const float* bias = (mat == 0) ? bq : ((mat == 1) ? bk : bv);
    float* out = (mat == 0) ? oq : ((mat == 1) ? ok : ov);
    gemm_core(A, Wp, bias, nullptr, out, 256, 0, blockIdx.x * 128, nblk);
}

// ---------------------------------------------------------------------------
// SIMT fp32 adjmul: out[bt,n,f0+f] = sum_m adj[n,m] * h[bt,m,f0+f]
// blockIdx.x = bt, blockIdx.y = f-chunk. 512 threads.
// ---------------------------------------------------------------------------
__global__ __launch_bounds__(512)
void adjmul_kernel(const float* __restrict__ h,
                   const float* __restrict__ adj,
                   float* __restrict__ out, int F_total, int F_chunk) {
    extern __shared__ float smf[];
    float* adj_s = smf;
    float* h_s   = smf + 10000;
    const int bt = blockIdx.x;
    const int f0 = blockIdx.y * F_chunk;
    const float* hp = h + (size_t)bt * Nz * F_total;
    float* op = out + (size_t)bt * Nz * F_total;

    for (int i = threadIdx.x; i < 10000; i += blockDim.x) adj_s[i] = adj[i];
    for (int i = threadIdx.x; i < Nz * F_chunk; i += blockDim.x) {
        int row = i / F_chunk, col = i - row * F_chunk;
        h_s[i] = hp[(size_t)row * F_total + f0 + col];
    }
    __syncthreads();

    const int nf2 = F_chunk >> 1;
    const int fp = threadIdx.x & (nf2 - 1);
    const int nl = threadIdx.x / nf2;
    const int nlanes = blockDim.x / nf2;
    const float2* h2 = (const float2*)h_s;
    float2* o2 = (float2*)op;
    const int ostride = F_total >> 1;
    const int obase = f0 >> 1;

    for (int n0 = nl * 4; n0 < Nz; n0 += nlanes * 4) {
        float2 a0c = make_float2(0.f, 0.f), a1c = a0c, a2c = a0c, a3c = a0c;
        #pragma unroll 4
        for (int m = 0; m < Nz; m++) {
            float2 hv = h2[m * nf2 + fp];
            float w0 = adj_s[(n0 + 0) * Nz + m];
            float w1 = adj_s[(n0 + 1) * Nz + m];
            float w2 = adj_s[(n0 + 2) * Nz + m];
            float w3 = adj_s[(n0 + 3) * Nz + m];
            a0c.x += w0 * hv.x; a0c.y += w0 * hv.y;
            a1c.x += w1 * hv.x; a1c.y += w1 * hv.y;
            a2c.x += w2 * hv.x; a2c.y += w2 * hv.y;
            a3c.x += w3 * hv.x; a3c.y += w3 * hv.y;
        }
        o2[(n0 + 0) * ostride + obase + fp] = a0c;
        o2[(n0 + 1) * ostride + obase + fp] = a1c;
        o2[(n0 + 2) * ostride + obase + fp] = a2c;
        o2[(n0 + 3) * ostride + obase + fp] = a3c;
    }
}

// ---------------------------------------------------------------------------
// Temporal attention (float4 scores)
// ---------------------------------------------------------------------------
#define QS 268   // floats per row: 16B aligned

__global__ __launch_bounds__(512)
void attn_kernel(const float* __restrict__ q, const float* __restrict__ k,
                 const float* __restrict__ v, float* __restrict__ out) {
    extern __shared__ float smf[];
    float* q_s = smf;
    float* k_s = q_s + Tz * QS;
    float* v_s = k_s + Tz * QS;
    float* p_s = v_s + Tz * QS;

    const int b = blockIdx.x / Nz;
    const int n = blockIdx.x % Nz;
    const size_t base = ((size_t)b * Tz * Nz + n) * Hz;
    const size_t tstride = (size_t)Nz * Hz;

    for (int i = threadIdx.x; i < Tz * Hz; i += blockDim.x) {
        int t = i >> 8; int hh = i & 255;
        q_s[t * QS + hh] = q[base + t * tstride + hh];
        k_s[t * QS + hh] = k[base + t * tstride + hh];
        v_s[t * QS + hh] = v[base + t * tstride + hh];
    }
    __syncthreads();

    if (threadIdx.x < Tz * Tz) {
        int t = threadIdx.x / Tz, s = threadIdx.x % Tz;
        const float4* q4 = (const float4*)(q_s + t * QS);
        const float4* k4 = (const float4*)(k_s + s * QS);
        float a0 = 0.f, a1 = 0.f;
        #pragma unroll 8
        for (int c = 0; c < 64; c += 2) {
            float4 qa = q4[c], ka = k4[c];
            float4 qb = q4[c + 1], kb = k4[c + 1];
            a0 += qa.x * ka.x + qa.y * ka.y + qa.z * ka.z + qa.w * ka.w;
            a1 += qb.x * kb.x + qb.y * kb.y + qb.z * kb.z + qb.w * kb.w;
        }
        p_s[t * 21 + s] = (a0 + a1) * 0.0625f;
    }
    __syncthreads();

    if (threadIdx.x < Tz) {
        int t = threadIdx.x;
        float mx = -1e30f;
        #pragma unroll
        for (int s = 0; s < Tz; s++) mx = fmaxf(mx, p_s[t * 21 + s]);
        float sum = 0.f;
        #pragma unroll
        for (int s = 0; s < Tz; s++) {
            float e = expf(p_s[t * 21 + s] - mx);
            p_s[t * 21 + s] = e; sum += e;
        }
        float inv = 1.f / sum;
        #pragma unroll
        for (int s = 0; s < Tz; s++) p_s[t * 21 + s] *= inv;
    }
    __syncthreads();

    const int hh = threadIdx.x & 255;
    const int th = threadIdx.x >> 8;
    for (int t = th * 10; t < th * 10 + 10; t++) {
        float acc = 0.f;
        #pragma unroll
        for (int s = 0; s < Tz; s++) acc += p_s[t * 21 + s] * v_s[s * QS + hh];
        out[base + t * tstride + hh] = acc;
    }
}

// ---------------------------------------------------------------------------
// LayerNorm
// ---------------------------------------------------------------------------
__global__ __launch_bounds__(256)
void ln_kernel(const float* __restrict__ a, const float* __restrict__ gamma,
               const float* __restrict__ beta, float* __restrict__ out) {
    __shared__ float ss[8], qq[8];
    const size_t row = blockIdx.x;
    const int t = threadIdx.x;
    float x = a[row * 256 + t];
    float s = x, q = x * x;
    #pragma unroll
    for (int o = 16; o > 0; o >>= 1) {
        s += __shfl_xor_sync(0xffffffffu, s, o);
        q += __shfl_xor_sync(0xffffffffu, q, o);
    }
    int w = t >> 5, l = t & 31;
    if (l == 0) { ss[w] = s; qq[w] = q; }
    __syncthreads();
    float S = 0.f, Q = 0.f;
    #pragma unroll
    for (int i = 0; i < 8; i++) { S += ss[i]; Q += qq[i]; }
    float mu = S * (1.f / 256.f);
    float var = Q * (1.f / 256.f) - mu * mu;
    float r = rsqrtf(var + 1e-5f);
    out[row * 256 + t] = (x - mu) * r * gamma[t] + beta[t];
}

// ---------------------------------------------------------------------------
// launch
// ---------------------------------------------------------------------------
extern "C" void kernel_launch(void* const* d_in, const int* in_sizes, int n_in,
                              void* d_out, int out_size) {
    const float* x    = (const float*)d_in[0];
    const float* adj  = (const float*)d_in[1];
    const float* W0   = (const float*)d_in[2];
    const float* b0   = (const float*)d_in[3];
    const float* W1   = (const float*)d_in[4];
    const float* b1   = (const float*)d_in[5];
    const float* W2   = (const float*)d_in[6];
    const float* b2   = (const float*)d_in[7];
    const float* Wq   = (const float*)d_in[8];
    const float* bq   = (const float*)d_in[9];
    const float* Wk   = (const float*)d_in[10];
    const float* bk   = (const float*)d_in[11];
    const float* Wv   = (const float*)d_in[12];
    const float* bv   = (const float*)d_in[13];
    const float* Wp   = (const float*)d_in[14];
    const float* bp   = (const float*)d_in[15];
    const float* gamma = (const float*)d_in[16];
    const float* beta  = (const float*)d_in[17];
    float* out = (float*)d_out;

    float *ph, *pg, *pq, *pk, *pv;
    uint8_t* wp;
    cudaGetSymbolAddress((void**)&ph, g_h);
    cudaGetSymbolAddress((void**)&pg, g_g);
    cudaGetSymbolAddress((void**)&pq, g_q);
    cudaGetSymbolAddress((void**)&pk, g_k);
    cudaGetSymbolAddress((void**)&pv, g_v);
    cudaGetSymbolAddress((void**)&wp, g_wpack);

    const int smem_adj64  = (10000 + Nz * Fz) * 4;       // 65.6 KB
    const int smem_adj128 = (10000 + Nz * 128) * 4;      // 91.2 KB
    const int smem_attn   = (3 * Tz * QS + Tz * 21) * 4; // ~66 KB
    cudaFuncSetAttribute(adjmul_kernel, cudaFuncAttributeMaxDynamicSharedMemorySize, smem_adj128);
    cudaFuncSetAttribute(attn_kernel,   cudaFuncAttributeMaxDynamicSharedMemorySize, smem_attn);
    cudaFuncSetAttribute(mma_gemm,      cudaFuncAttributeMaxDynamicSharedMemorySize, SMEM_GEMM);
    cudaFuncSetAttribute(qkv_gemm,      cudaFuncAttributeMaxDynamicSharedMemorySize, SMEM_GEMM);

    // pack all weights (fp16 hi/lo, swizzled ldmatrix layout)
    W7 ws;
    ws.w[0] = W0; ws.w[1] = W1; ws.w[2] = W2; ws.w[3] = Wq;
    ws.w[4] = Wk; ws.w[5] = Wv; ws.w[6] = Wp;
    pack_w_all<<<dim3(256, 7), 256>>>(ws, wp);

    const int BT = Bz * Tz;                 // 1280
    const int M = Bz * Tz * Nz;             // 128000
    dim3 gg(M / 128, 2);

    // GCN layer 0 (F=64 -> H=256)
    adjmul_kernel<<<dim3(BT, 1), 512, smem_adj64>>>(x, adj, pg, Fz, Fz);
    mma_gemm<<<gg, 256, SMEM_GEMM>>>(pg, wp + 0 * WPACK_STRIDE, b0, nullptr, ph, Fz, 1);
    // GCN layer 1 (residual)
    adjmul_kernel<<<dim3(BT, 2), 512, smem_adj128>>>(ph, adj, pg, Hz, 128);
    mma_gemm<<<gg, 256, SMEM_GEMM>>>(pg, wp + 1 * WPACK_STRIDE, b1, ph, ph, Hz, 1);
    // GCN layer 2 (residual)
    adjmul_kernel<<<dim3(BT, 2), 512, smem_adj128>>>(ph, adj, pg, Hz, 128);
    mma_gemm<<<gg, 256, SMEM_GEMM>>>(pg, wp + 2 * WPACK_STRIDE, b2, ph, ph, Hz, 1);
    // Q, K, V fused launch
    qkv_gemm<<<dim3(M / 128, 6), 256, SMEM_GEMM>>>(ph, wp, bq, bk, bv, pq, pk, pv);
    // attention
    attn_kernel<<<Bz * Nz, 512, smem_attn>>>(pq, pk, pv, pg);
    // output projection
    mma_gemm<<<gg, 256, SMEM_GEMM>>>(pg, wp + 6 * WPACK_STRIDE, bp, nullptr, pq, Hz, 0);
    // layernorm
    ln_kernel<<<M, 256>>>(pq, gamma, beta, out);
}

// round 8
// speedup vs baseline: 2.0547x; 1.2737x over previous
#include <cuda_runtime.h>
#include <cuda_fp16.h>
#include <math.h>
#include <stdint.h>

// B=64, T=20, N=100, F=64, H=256
#define Bz 64
#define Tz 20
#define Nz 100
#define Fz 64
#define Hz 256
#define ELEMS (64UL*20UL*100UL*256UL)   // 32,768,000

__device__ float g_h[ELEMS];
__device__ float g_g[ELEMS];
__device__ float g_q[ELEMS];
__device__ float g_k[ELEMS];
__device__ float g_v[ELEMS];
// Pre-split A: fp16 hi/lo in exact smem-tile image. 128000x256 x 4B = 131MB
__device__ uint8_t g_asplit[ELEMS * 4];
#define WPACK_STRIDE 262144
__device__ uint8_t g_wpack[7 * WPACK_STRIDE];

// ---------------------------------------------------------------------------
// helpers
// ---------------------------------------------------------------------------
__device__ __forceinline__ uint32_t smem_u32(const void* p) {
    uint32_t a;
    asm("{ .reg .u64 t; cvta.to.shared.u64 t, %1; cvt.u32.u64 %0, t; }" : "=r"(a) : "l"(p));
    return a;
}
__device__ __forceinline__ void ldsm_x4(uint32_t* r, uint32_t addr) {
    asm volatile("ldmatrix.sync.aligned.m8n8.x4.shared.b16 {%0,%1,%2,%3}, [%4];"
                 : "=r"(r[0]), "=r"(r[1]), "=r"(r[2]), "=r"(r[3]) : "r"(addr));
}
__device__ __forceinline__ void ldsm_x2(uint32_t* r, uint32_t addr) {
    asm volatile("ldmatrix.sync.aligned.m8n8.x2.shared.b16 {%0,%1}, [%2];"
                 : "=r"(r[0]), "=r"(r[1]) : "r"(addr));
}
__device__ __forceinline__ void mma16816(float* d, const uint32_t* a, const uint32_t* b) {
    asm volatile(
        "mma.sync.aligned.m16n8k16.row.col.f32.f16.f16.f32 "
        "{%0,%1,%2,%3}, {%4,%5,%6,%7}, {%8,%9}, {%0,%1,%2,%3};"
        : "+f"(d[0]), "+f"(d[1]), "+f"(d[2]), "+f"(d[3])
        : "r"(a[0]), "r"(a[1]), "r"(a[2]), "r"(a[3]), "r"(b[0]), "r"(b[1]));
}
__device__ __forceinline__ void split_h2(float x, float y, uint32_t& hi, uint32_t& lo) {
    __half h0 = __float2half(x), h1 = __float2half(y);
    __half l0 = __float2half(x - __half2float(h0));
    __half l1 = __float2half(y - __half2float(h1));
    __half2 hp = make_half2(h0, h1), lp = make_half2(l0, l1);
    hi = *(uint32_t*)&hp; lo = *(uint32_t*)&lp;
}
__device__ __forceinline__ void cp16(uint32_t saddr, const void* gaddr) {
    asm volatile("cp.async.cg.shared.global [%0], [%1], 16;" :: "r"(saddr), "l"(gaddr));
}

// ---------------------------------------------------------------------------
// Packing: all 7 weight matrices in one launch
// ---------------------------------------------------------------------------
struct W7 { const float* w[7]; };

__global__ void pack_w_all(W7 ws, uint8_t* __restrict__ dst) {
    int mat = blockIdx.y;
    int K = (mat == 0) ? 64 : 256;
    int i = blockIdx.x * blockDim.x + threadIdx.x;
    if (i >= K * 256) return;
    int k = i >> 8, n = i & 255;
    float v = ws.w[mat][i];
    __half h = __float2half(v);
    __half l = __float2half(v - __half2float(h));
    int nblk = n >> 7, rn = n & 127, chunk = k >> 6, kl = k & 63;
    int ncK = K >> 6;
    uint32_t boff = (uint32_t)(rn * 128 + ((((kl >> 3) ^ (rn & 7))) << 4) + (kl & 7) * 2);
    uint8_t* tile = dst + (size_t)mat * WPACK_STRIDE + (size_t)(nblk * ncK + chunk) * 32768;
    *(__half*)(tile + boff) = h;
    *(__half*)(tile + 16384 + boff) = l;
}

// ---------------------------------------------------------------------------
// split_a: A[M,K] fp32 -> per (mtile 128 rows, kchunk 64) 32KB block:
// [hi 16KB swizzled][lo 16KB swizzled], matching the GEMM smem image.
// Each thread handles 8 consecutive k (one 16B output line in hi and lo).
// ---------------------------------------------------------------------------
__global__ void split_a_kernel(const float* __restrict__ A, uint8_t* __restrict__ dst, int K) {
    int idx = blockIdx.x * blockDim.x + threadIdx.x;
    int kq = K >> 3;                       // 16B lines per row
    int m = idx / kq, kc8 = idx - m * kq;  // kc8: which 8-k group
    const float4* src = (const float4*)&A[(size_t)m * K + kc8 * 8];
    float4 v0 = src[0], v1 = src[1];
    uint32_t hi[4], lo[4];
    split_h2(v0.x, v0.y, hi[0], lo[0]);
    split_h2(v0.z, v0.w, hi[1], lo[1]);
    split_h2(v1.x, v1.y, hi[2], lo[2]);
    split_h2(v1.z, v1.w, hi[3], lo[3]);
    int mtile = m >> 7, row = m & 127;
    int chunk = kc8 >> 3, kc = kc8 & 7;
    uint32_t boff = (uint32_t)(row * 128 + ((kc ^ (row & 7)) << 4));
    uint8_t* block = dst + (size_t)(mtile * (K >> 6) + chunk) * 32768;
    *(uint4*)(block + boff) = make_uint4(hi[0], hi[1], hi[2], hi[3]);
    *(uint4*)(block + 16384 + boff) = make_uint4(lo[0], lo[1], lo[2], lo[3]);
}

// ---------------------------------------------------------------------------
// Pipelined warp-MMA fp16x3 GEMM: out[M,256] = op(Asplit @ W + bias) (+res)
// CTA 128x128, 8 warps, double-buffered cp.async stages (A 32KB + B 32KB).
// ---------------------------------------------------------------------------
#define STAGE_BYTES 65536
#define SMEM_GEMM (512 + 2 * STAGE_BYTES)

__device__ __forceinline__ void gemm_core(
    const uint8_t* __restrict__ As, const uint8_t* __restrict__ Wp,
    const float* __restrict__ bias, const float* res,
    float* out, int K, int do_relu, int mtile, int nblk)
{
    extern __shared__ char sm[];
    const uint32_t sbase = smem_u32(sm);
    const int tid = threadIdx.x;
    const int warp = tid >> 5, lane = tid & 31;
    const int m0 = mtile * 128;
    const int n0 = nblk * 128;
    const int nc = K >> 6;

    if (tid < 128) ((float*)sm)[tid] = bias[n0 + tid];

    const uint8_t* Abase = As + (size_t)mtile * (nc * 32768);
    const uint8_t* Bbase = Wp + (size_t)nblk * (nc * 32768);

    // stage chunk c into buffer c&1
    auto issue = [&](int c) {
        uint32_t sa = sbase + 512 + (c & 1) * STAGE_BYTES;
        const uint8_t* ga = Abase + (size_t)c * 32768 + tid * 16;
        const uint8_t* gb = Bbase + (size_t)c * 32768 + tid * 16;
        #pragma unroll
        for (int i = 0; i < 8; i++)
            cp16(sa + tid * 16 + i * 4096, ga + i * 4096);
        #pragma unroll
        for (int i = 0; i < 8; i++)
            cp16(sa + 32768 + tid * 16 + i * 4096, gb + i * 4096);
        asm volatile("cp.async.commit_group;" ::: "memory");
    };

    float acc[4][4][4] = {};
    const int wm = warp >> 2, wn = warp & 3;
    const int m_base = wm * 64, n_base = wn * 32;
    const int amat = lane >> 3, ar = lane & 7;
    const int arow_b = m_base + (amat & 1) * 8 + ar;
    const int asel = amat >> 1;
    const int l16 = lane & 15;
    const int bmat = l16 >> 3, br = l16 & 7;

    issue(0);
    for (int c = 0; c < nc; c++) {
        if (c + 1 < nc) {
            issue(c + 1);
            asm volatile("cp.async.wait_group 1;" ::: "memory");
        } else {
            asm volatile("cp.async.wait_group 0;" ::: "memory");
        }
        __syncthreads();
        const uint32_t sb = sbase + 512 + (c & 1) * STAGE_BYTES;

        #pragma unroll
        for (int ks = 0; ks < 4; ks++) {
            uint32_t bh[4][2], bl[4][2];
            #pragma unroll
            for (int nt = 0; nt < 4; nt++) {
                int brow = n_base + nt * 8 + br;
                uint32_t boffs = (uint32_t)(brow * 128 + (((ks * 2 + bmat) ^ (brow & 7)) << 4));
                ldsm_x2(bh[nt], sb + 32768 + boffs);
                ldsm_x2(bl[nt], sb + 49152 + boffs);
            }
            #pragma unroll
            for (int mt = 0; mt < 4; mt++) {
                int arow = arow_b + mt * 16;
                uint32_t aoffs = (uint32_t)(arow * 128 + (((ks * 2 + asel) ^ (arow & 7)) << 4));
                uint32_t ah[4], al[4];
                ldsm_x4(ah, sb + aoffs);
                ldsm_x4(al, sb + 16384 + aoffs);
                #pragma unroll
                for (int nt = 0; nt < 4; nt++) {
                    mma16816(acc[mt][nt], ah, bh[nt]);
                    mma16816(acc[mt][nt], ah, bl[nt]);
                    mma16816(acc[mt][nt], al, bh[nt]);
                }
            }
        }
        __syncthreads();
    }

    const float* bias_s = (const float*)sm;
    const int g = lane >> 2, tc = lane & 3;
    #pragma unroll
    for (int mt = 0; mt < 4; mt++) {
        int r0 = m0 + m_base + mt * 16 + g;
        #pragma unroll
        for (int nt = 0; nt < 4; nt++) {
            int cl = n_base + nt * 8 + tc * 2;
            float b0 = bias_s[cl], b1 = bias_s[cl + 1];
            float2 o0, o1;
            o0.x = acc[mt][nt][0] + b0; o0.y = acc[mt][nt][1] + b1;
            o1.x = acc[mt][nt][2] + b0; o1.y = acc[mt][nt][3] + b1;
            if (do_relu) {
                o0.x = fmaxf(o0.x, 0.f); o0.y = fmaxf(o0.y, 0.f);
                o1.x = fmaxf(o1.x, 0.f); o1.y = fmaxf(o1.y, 0.f);
            }
            size_t i0 = (size_t)r0 * 256 + n0 + cl;
            size_t i1 = (size_t)(r0 + 8) * 256 + n0 + cl;
            if (res) {
                float2 rv0 = *(const float2*)&res[i0];
                float2 rv1 = *(const float2*)&res[i1];
                o0.x += rv0.x; o0.y += rv0.y;
                o1.x += rv1.x; o1.y += rv1.y;
            }
            *(float2*)&out[i0] = o0;
            *(float2*)&out[i1] = o1;
        }
    }
}

__global__ __launch_bounds__(256)
void mma_gemm(const uint8_t* __restrict__ As, const uint8_t* __restrict__ Wp,
              const float* __restrict__ bias, const float* res,
              float* out, int K, int do_relu) {
    gemm_core(As, Wp, bias, res, out, K, do_relu, blockIdx.x, blockIdx.y);
}

__global__ __launch_bounds__(256)
void qkv_gemm(const uint8_t* __restrict__ As, const uint8_t* __restrict__ WpBase,
              const float* __restrict__ bq, const float* __restrict__ bk,
              const float* __restrict__ bv,
              float* oq, float* ok, float* ov) {
    int mat = blockIdx.y >> 1, nblk = blockIdx.y & 1;
    const uint8_t* Wp = WpBase + (size_t)(3 + mat) * WPACK_STRIDE;
    const float* bias = (mat == 0) ? bq : ((mat == 1) ? bk : bv);
    float* out = (mat == 0) ? oq : ((mat == 1) ? ok : ov);
    gemm_core(As, Wp, bias, nullptr, out, 256, 0, blockIdx.x, nblk);
}

// ---------------------------------------------------------------------------
// SIMT fp32 adjmul, 4n x 4f register tile, F_chunk = 64.
// blockIdx.x = bt, blockIdx.y = f-chunk. 512 threads.
// ---------------------------------------------------------------------------
__global__ __launch_bounds__(512)
void adjmul_kernel(const float* __restrict__ h,
                   const float* __restrict__ adj,
                   float* __restrict__ out, int F_total) {
    extern __shared__ float smf[];
    float* adj_s = smf;            // 100*100
    float* h_s   = smf + 10000;    // 100*64
    const int bt = blockIdx.x;
    const int f0 = blockIdx.y * 64;
    const float* hp = h + (size_t)bt * Nz * F_total;
    float* op = out + (size_t)bt * Nz * F_total;

    // stage adj (float4) and h chunk
    {
        const float4* a4 = (const float4*)adj;
        float4* s4 = (float4*)adj_s;
        for (int i = threadIdx.x; i < 2500; i += 512) s4[i] = a4[i];
        for (int i = threadIdx.x; i < 1600; i += 512) {
            int row = i >> 4, c4 = i & 15;
            ((float4*)h_s)[i] = *(const float4*)&hp[(size_t)row * F_total + f0 + c4 * 4];
        }
    }
    __syncthreads();

    const int fq = threadIdx.x & 15;       // f quad: 16 x 4 = 64
    const int nl = threadIdx.x >> 4;       // 32 n-lanes x 4 rows = 128 >= 100
    const int n0 = nl * 4;
    if (n0 >= Nz) return;
    const float4* h4 = (const float4*)h_s;

    float4 a0 = make_float4(0.f, 0.f, 0.f, 0.f), a1 = a0, a2 = a0, a3 = a0;
    #pragma unroll 2
    for (int m = 0; m < Nz; m++) {
        float4 hv = h4[m * 16 + fq];
        float w0 = adj_s[(n0 + 0) * Nz + m];
        float w1 = adj_s[(n0 + 1) * Nz + m];
        float w2 = adj_s[(n0 + 2) * Nz + m];
        float w3 = adj_s[(n0 + 3) * Nz + m];
        a0.x += w0 * hv.x; a0.y += w0 * hv.y; a0.z += w0 * hv.z; a0.w += w0 * hv.w;
        a1.x += w1 * hv.x; a1.y += w1 * hv.y; a1.z += w1 * hv.z; a1.w += w1 * hv.w;
        a2.x += w2 * hv.x; a2.y += w2 * hv.y; a2.z += w2 * hv.z; a2.w += w2 * hv.w;
        a3.x += w3 * hv.x; a3.y += w3 * hv.y; a3.z += w3 * hv.z; a3.w += w3 * hv.w;
    }
    size_t ob = (size_t)(n0) * F_total + f0 + fq * 4;
    *(float4*)&op[ob] = a0;
    *(float4*)&op[ob + F_total] = a1;
    *(float4*)&op[ob + 2 * F_total] = a2;
    *(float4*)&op[ob + 3 * F_total] = a3;
}

// ---------------------------------------------------------------------------
// Temporal attention (float4 scores)
// ---------------------------------------------------------------------------
#define QS 268

__global__ __launch_bounds__(512)
void attn_kernel(const float* __restrict__ q, const float* __restrict__ k,
                 const float* __restrict__ v, float* __restrict__ out) {
    extern __shared__ float smf[];
    float* q_s = smf;
    float* k_s = q_s + Tz * QS;
    float* v_s = k_s + Tz * QS;
    float* p_s = v_s + Tz * QS;

    const int b = blockIdx.x / Nz;
    const int n = blockIdx.x % Nz;
    const size_t base = ((size_t)b * Tz * Nz + n) * Hz;
    const size_t tstride = (size_t)Nz * Hz;

    for (int i = threadIdx.x; i < Tz * Hz; i += blockDim.x) {
        int t = i >> 8; int hh = i & 255;
        q_s[t * QS + hh] = q[base + t * tstride + hh];
        k_s[t * QS + hh] = k[base + t * tstride + hh];
        v_s[t * QS + hh] = v[base + t * tstride + hh];
    }
    __syncthreads();

    if (threadIdx.x < Tz * Tz) {
        int t = threadIdx.x / Tz, s = threadIdx.x % Tz;
        const float4* q4 = (const float4*)(q_s + t * QS);
        const float4* k4 = (const float4*)(k_s + s * QS);
        float a0 = 0.f, a1 = 0.f;
        #pragma unroll 8
        for (int c = 0; c < 64; c += 2) {
            float4 qa = q4[c], ka = k4[c];
            float4 qb = q4[c + 1], kb = k4[c + 1];
            a0 += qa.x * ka.x + qa.y * ka.y + qa.z * ka.z + qa.w * ka.w;
            a1 += qb.x * kb.x + qb.y * kb.y + qb.z * kb.z + qb.w * kb.w;
        }
        p_s[t * 21 + s] = (a0 + a1) * 0.0625f;
    }
    __syncthreads();

    if (threadIdx.x < Tz) {
        int t = threadIdx.x;
        float mx = -1e30f;
        #pragma unroll
        for (int s = 0; s < Tz; s++) mx = fmaxf(mx, p_s[t * 21 + s]);
        float sum = 0.f;
        #pragma unroll
        for (int s = 0; s < Tz; s++) {
            float e = expf(p_s[t * 21 + s] - mx);
            p_s[t * 21 + s] = e; sum += e;
        }
        float inv = 1.f / sum;
        #pragma unroll
        for (int s = 0; s < Tz; s++) p_s[t * 21 + s] *= inv;
    }
    __syncthreads();

    const int hh = threadIdx.x & 255;
    const int th = threadIdx.x >> 8;
    for (int t = th * 10; t < th * 10 + 10; t++) {
        float acc = 0.f;
        #pragma unroll
        for (int s = 0; s < Tz; s++) acc += p_s[t * 21 + s] * v_s[s * QS + hh];
        out[base + t * tstride + hh] = acc;
    }
}

// ---------------------------------------------------------------------------
// LayerNorm
// ---------------------------------------------------------------------------
__global__ __launch_bounds__(256)
void ln_kernel(const float* __restrict__ a, const float* __restrict__ gamma,
               const float* __restrict__ beta, float* __restrict__ out) {
    __shared__ float ss[8], qq[8];
    const size_t row = blockIdx.x;
    const int t = threadIdx.x;
    float x = a[row * 256 + t];
    float s = x, q = x * x;
    #pragma unroll
    for (int o = 16; o > 0; o >>= 1) {
        s += __shfl_xor_sync(0xffffffffu, s, o);
        q += __shfl_xor_sync(0xffffffffu, q, o);
    }
    int w = t >> 5, l = t & 31;
    if (l == 0) { ss[w] = s; qq[w] = q; }
    __syncthreads();
    float S = 0.f, Q = 0.f;
    #pragma unroll
    for (int i = 0; i < 8; i++) { S += ss[i]; Q += qq[i]; }
    float mu = S * (1.f / 256.f);
    float var = Q * (1.f / 256.f) - mu * mu;
    float r = rsqrtf(var + 1e-5f);
    out[row * 256 + t] = (x - mu) * r * gamma[t] + beta[t];
}

// ---------------------------------------------------------------------------
// launch
// ---------------------------------------------------------------------------
extern "C" void kernel_launch(void* const* d_in, const int* in_sizes, int n_in,
                              void* d_out, int out_size) {
    const float* x    = (const float*)d_in[0];
    const float* adj  = (const float*)d_in[1];
    const float* W0   = (const float*)d_in[2];
    const float* b0   = (const float*)d_in[3];
    const float* W1   = (const float*)d_in[4];
    const float* b1   = (const float*)d_in[5];
    const float* W2   = (const float*)d_in[6];
    const float* b2   = (const float*)d_in[7];
    const float* Wq   = (const float*)d_in[8];
    const float* bq   = (const float*)d_in[9];
    const float* Wk   = (const float*)d_in[10];
    const float* bk   = (const float*)d_in[11];
    const float* Wv   = (const float*)d_in[12];
    const float* bv   = (const float*)d_in[13];
    const float* Wp   = (const float*)d_in[14];
    const float* bp   = (const float*)d_in[15];
    const float* gamma = (const float*)d_in[16];
    const float* beta  = (const float*)d_in[17];
    float* out = (float*)d_out;

    float *ph, *pg, *pq, *pk, *pv;
    uint8_t *wp, *as;
    cudaGetSymbolAddress((void**)&ph, g_h);
    cudaGetSymbolAddress((void**)&pg, g_g);
    cudaGetSymbolAddress((void**)&pq, g_q);
    cudaGetSymbolAddress((void**)&pk, g_k);
    cudaGetSymbolAddress((void**)&pv, g_v);
    cudaGetSymbolAddress((void**)&wp, g_wpack);
    cudaGetSymbolAddress((void**)&as, g_asplit);

    const int smem_adj  = (10000 + Nz * 64) * 4;         // 65.6 KB
    const int smem_attn = (3 * Tz * QS + Tz * 21) * 4;   // ~66 KB
    cudaFuncSetAttribute(adjmul_kernel, cudaFuncAttributeMaxDynamicSharedMemorySize, smem_adj);
    cudaFuncSetAttribute(attn_kernel,   cudaFuncAttributeMaxDynamicSharedMemorySize, smem_attn);
    cudaFuncSetAttribute(mma_gemm,      cudaFuncAttributeMaxDynamicSharedMemorySize, SMEM_GEMM);
    cudaFuncSetAttribute(qkv_gemm,      cudaFuncAttributeMaxDynamicSharedMemorySize, SMEM_GEMM);

    W7 ws;
    ws.w[0] = W0; ws.w[1] = W1; ws.w[2] = W2; ws.w[3] = Wq;
    ws.w[4] = Wk; ws.w[5] = Wv; ws.w[6] = Wp;
    pack_w_all<<<dim3(256, 7), 256>>>(ws, wp);

    const int BT = Bz * Tz;                 // 1280
    const int M = Bz * Tz * Nz;             // 128000
    dim3 gg(M / 128, 2);
    const int splitg256 = (M * 256 / 8) / 256;  // 16000
    const int splitg64  = (M * 64 / 8) / 256;   // 4000

    // GCN layer 0 (F=64 -> H=256)
    adjmul_kernel<<<dim3(BT, 1), 512, smem_adj>>>(x, adj, pg, Fz);
    split_a_kernel<<<splitg64, 256>>>(pg, as, Fz);
    mma_gemm<<<gg, 256, SMEM_GEMM>>>(as, wp + 0 * WPACK_STRIDE, b0, nullptr, ph, Fz, 1);
    // GCN layer 1 (residual)
    adjmul_kernel<<<dim3(BT, 4), 512, smem_adj>>>(ph, adj, pg, Hz);
    split_a_kernel<<<splitg256, 256>>>(pg, as, Hz);
    mma_gemm<<<gg, 256, SMEM_GEMM>>>(as, wp + 1 * WPACK_STRIDE, b1, ph, ph, Hz, 1);
    // GCN layer 2 (residual)
    adjmul_kernel<<<dim3(BT, 4), 512, smem_adj>>>(ph, adj, pg, Hz);
    split_a_kernel<<<splitg256, 256>>>(pg, as, Hz);
    mma_gemm<<<gg, 256, SMEM_GEMM>>>(as, wp + 2 * WPACK_STRIDE, b2, ph, ph, Hz, 1);
    // Q, K, V fused launch (split once, reused 6x)
    split_a_kernel<<<splitg256, 256>>>(ph, as, Hz);
    qkv_gemm<<<dim3(M / 128, 6), 256, SMEM_GEMM>>>(as, wp, bq, bk, bv, pq, pk, pv);
    // attention
    attn_kernel<<<Bz * Nz, 512, smem_attn>>>(pq, pk, pv, pg);
    // output projection
    split_a_kernel<<<splitg256, 256>>>(pg, as, Hz);
    mma_gemm<<<gg, 256, SMEM_GEMM>>>(as, wp + 6 * WPACK_STRIDE, bp, nullptr, pq, Hz, 0);
    // layernorm
    ln_kernel<<<M, 256>>>(pq, gamma, beta, out);
}

// round 10
// speedup vs baseline: 2.0725x; 1.0087x over previous
#include <cuda_runtime.h>
#include <cuda_fp16.h>
#include <math.h>
#include <stdint.h>

// B=64, T=20, N=100, F=64, H=256
#define Bz 64
#define Tz 20
#define Nz 100
#define Fz 64
#define Hz 256
#define ELEMS (64UL*20UL*100UL*256UL)   // 32,768,000

__device__ float g_h[ELEMS];
__device__ float g_g[ELEMS];           // reused as split buffer #2 (131MB)
__device__ float g_q[ELEMS];
__device__ float g_k[ELEMS];
__device__ float g_v[ELEMS];
__device__ uint8_t g_asplit[ELEMS * 4];  // split buffer #1
#define WPACK_STRIDE 262144
__device__ uint8_t g_wpack[7 * WPACK_STRIDE];

// ---------------------------------------------------------------------------
// helpers
// ---------------------------------------------------------------------------
__device__ __forceinline__ uint32_t smem_u32(const void* p) {
    uint32_t a;
    asm("{ .reg .u64 t; cvta.to.shared.u64 t, %1; cvt.u32.u64 %0, t; }" : "=r"(a) : "l"(p));
    return a;
}
__device__ __forceinline__ void ldsm_x4(uint32_t* r, uint32_t addr) {
    asm volatile("ldmatrix.sync.aligned.m8n8.x4.shared.b16 {%0,%1,%2,%3}, [%4];"
                 : "=r"(r[0]), "=r"(r[1]), "=r"(r[2]), "=r"(r[3]) : "r"(addr));
}
__device__ __forceinline__ void ldsm_x2(uint32_t* r, uint32_t addr) {
    asm volatile("ldmatrix.sync.aligned.m8n8.x2.shared.b16 {%0,%1}, [%2];"
                 : "=r"(r[0]), "=r"(r[1]) : "r"(addr));
}
__device__ __forceinline__ void mma16816(float* d, const uint32_t* a, const uint32_t* b) {
    asm volatile(
        "mma.sync.aligned.m16n8k16.row.col.f32.f16.f16.f32 "
        "{%0,%1,%2,%3}, {%4,%5,%6,%7}, {%8,%9}, {%0,%1,%2,%3};"
        : "+f"(d[0]), "+f"(d[1]), "+f"(d[2]), "+f"(d[3])
        : "r"(a[0]), "r"(a[1]), "r"(a[2]), "r"(a[3]), "r"(b[0]), "r"(b[1]));
}
__device__ __forceinline__ void split_h2(float x, float y, uint32_t& hi, uint32_t& lo) {
    __half h0 = __float2half(x), h1 = __float2half(y);
    __half l0 = __float2half(x - __half2float(h0));
    __half l1 = __float2half(y - __half2float(h1));
    __half2 hp = make_half2(h0, h1), lp = make_half2(l0, l1);
    hi = *(uint32_t*)&hp; lo = *(uint32_t*)&lp;
}
__device__ __forceinline__ void cp16(uint32_t saddr, const void* gaddr) {
    asm volatile("cp.async.cg.shared.global [%0], [%1], 16;" :: "r"(saddr), "l"(gaddr));
}

// ---------------------------------------------------------------------------
// Packing: all 7 weight matrices in one launch
// ---------------------------------------------------------------------------
struct W7 { const float* w[7]; };

__global__ void pack_w_all(W7 ws, uint8_t* __restrict__ dst) {
    int mat = blockIdx.y;
    int K = (mat == 0) ? 64 : 256;
    int i = blockIdx.x * blockDim.x + threadIdx.x;
    if (i >= K * 256) return;
    int k = i >> 8, n = i & 255;
    float v = ws.w[mat][i];
    __half h = __float2half(v);
    __half l = __float2half(v - __half2float(h));
    int nblk = n >> 7, rn = n & 127, chunk = k >> 6, kl = k & 63;
    int ncK = K >> 6;
    uint32_t boff = (uint32_t)(rn * 128 + ((((kl >> 3) ^ (rn & 7))) << 4) + (kl & 7) * 2);
    uint8_t* tile = dst + (size_t)mat * WPACK_STRIDE + (size_t)(nblk * ncK + chunk) * 32768;
    *(__half*)(tile + boff) = h;
    *(__half*)(tile + 16384 + boff) = l;
}

// ---------------------------------------------------------------------------
// Pipelined warp-MMA fp16x3 GEMM: 128x256 CTA tile, 512 thr (16 warps 2m x 8n)
// A pre-split; B prepacked; 2-stage cp.async (96KB/stage).
// Output: fp32 (+bias/relu/res) or split-image (for GEMM-chained consumers).
// ---------------------------------------------------------------------------
#define STG_B 98304   // 96KB per stage: A hi/lo 32K | B0 hi/lo 32K | B1 hi/lo 32K
#define SMEM_GEMM (1024 + 2 * STG_B)

__device__ __forceinline__ void gemm_core(
    const uint8_t* __restrict__ As, const uint8_t* __restrict__ Wp,
    const float* __restrict__ bias, const float* res,
    float* out, uint8_t* out_split, int K, int do_relu, int mtile)
{
    extern __shared__ char sm[];
    const uint32_t sbase = smem_u32(sm);
    const int tid = threadIdx.x;
    const int warp = tid >> 5, lane = tid & 31;
    const int m0 = mtile * 128;
    const int nc = K >> 6;

    if (tid < 256) ((float*)sm)[tid] = bias[tid];

    const uint8_t* Abase = As + (size_t)mtile * (nc * 32768);

    auto issue = [&](int c) {
        uint32_t sa = sbase + 1024 + (c & 1) * STG_B;
        const uint8_t* ga = Abase + (size_t)c * 32768 + tid * 16;
        const uint8_t* gb0 = Wp + (size_t)c * 32768 + tid * 16;
        const uint8_t* gb1 = Wp + (size_t)(nc + c) * 32768 + tid * 16;
        #pragma unroll
        for (int i = 0; i < 4; i++) cp16(sa + tid * 16 + i * 8192, ga + i * 8192);
        #pragma unroll
        for (int i = 0; i < 4; i++) cp16(sa + 32768 + tid * 16 + i * 8192, gb0 + i * 8192);
        #pragma unroll
        for (int i = 0; i < 4; i++) cp16(sa + 65536 + tid * 16 + i * 8192, gb1 + i * 8192);
        asm volatile("cp.async.commit_group;" ::: "memory");
    };

    float acc[4][4][4] = {};
    const int wm = warp >> 3, wn = warp & 7;
    const int m_base = wm * 64, n_base = wn * 32;
    const int amat = lane >> 3, ar = lane & 7;
    const int arow_b = m_base + (amat & 1) * 8 + ar;
    const int asel = amat >> 1;
    const int l16 = lane & 15;
    const int bmat = l16 >> 3, br = l16 & 7;
    const uint32_t bofs_base = 32768 + (uint32_t)(wn >> 2) * 32768;
    const int brow_loc = (wn & 3) * 32;

    issue(0);
    for (int c = 0; c < nc; c++) {
        if (c + 1 < nc) {
            issue(c + 1);
            asm volatile("cp.async.wait_group 1;" ::: "memory");
        } else {
            asm volatile("cp.async.wait_group 0;" ::: "memory");
        }
        __syncthreads();
        const uint32_t sb = sbase + 1024 + (c & 1) * STG_B;

        #pragma unroll
        for (int ks = 0; ks < 4; ks++) {
            uint32_t bh[4][2], bl[4][2];
            #pragma unroll
            for (int nt = 0; nt < 4; nt++) {
                int brow = brow_loc + nt * 8 + br;
                uint32_t boffs = (uint32_t)(brow * 128 + (((ks * 2 + bmat) ^ (brow & 7)) << 4));
                ldsm_x2(bh[nt], sb + bofs_base + boffs);
                ldsm_x2(bl[nt], sb + bofs_base + 16384 + boffs);
            }
            #pragma unroll
            for (int mt = 0; mt < 4; mt++) {
                int arow = arow_b + mt * 16;
                uint32_t aoffs = (uint32_t)(arow * 128 + (((ks * 2 + asel) ^ (arow & 7)) << 4));
                uint32_t ah[4], al[4];
                ldsm_x4(ah, sb + aoffs);
                ldsm_x4(al, sb + 16384 + aoffs);
                #pragma unroll
                for (int nt = 0; nt < 4; nt++) {
                    mma16816(acc[mt][nt], ah, bh[nt]);
                    mma16816(acc[mt][nt], ah, bl[nt]);
                    mma16816(acc[mt][nt], al, bh[nt]);
                }
            }
        }
        __syncthreads();
    }

    const float* bias_s = (const float*)sm;
    const int g = lane >> 2, tc = lane & 3;
    #pragma unroll
    for (int mt = 0; mt < 4; mt++) {
        int rl0 = m_base + mt * 16 + g;       // row within 128-tile
        #pragma unroll
        for (int nt = 0; nt < 4; nt++) {
            int cl = n_base + nt * 8 + tc * 2;  // col 0..255
            float b0 = bias_s[cl], b1 = bias_s[cl + 1];
            float2 o0, o1;
            o0.x = acc[mt][nt][0] + b0; o0.y = acc[mt][nt][1] + b1;
            o1.x = acc[mt][nt][2] + b0; o1.y = acc[mt][nt][3] + b1;
            if (do_relu) {
                o0.x = fmaxf(o0.x, 0.f); o0.y = fmaxf(o0.y, 0.f);
                o1.x = fmaxf(o1.x, 0.f); o1.y = fmaxf(o1.y, 0.f);
            }
            size_t i0 = (size_t)(m0 + rl0) * 256 + cl;
            size_t i1 = (size_t)(m0 + rl0 + 8) * 256 + cl;
            if (res) {
                float2 rv0 = *(const float2*)&res[i0];
                float2 rv1 = *(const float2*)&res[i1];
                o0.x += rv0.x; o0.y += rv0.y;
                o1.x += rv1.x; o1.y += rv1.y;
            }
            if (out_split) {
                // write split image (K=256): 4B hi + 4B lo per row
                int chunk = cl >> 6, kc = (cl >> 3) & 7, inner = (cl & 7) * 2;
                uint8_t* block = out_split + (size_t)(mtile * 4 + chunk) * 32768;
                uint32_t hi, lo;
                int r = rl0;
                uint32_t boff = (uint32_t)(r * 128 + ((kc ^ (r & 7)) << 4) + inner);
                split_h2(o0.x, o0.y, hi, lo);
                *(uint32_t*)(block + boff) = hi;
                *(uint32_t*)(block + 16384 + boff) = lo;
                r = rl0 + 8;
                boff = (uint32_t)(r * 128 + ((kc ^ (r & 7)) << 4) + inner);
                split_h2(o1.x, o1.y, hi, lo);
                *(uint32_t*)(block + boff) = hi;
                *(uint32_t*)(block + 16384 + boff) = lo;
            } else {
                *(float2*)&out[i0] = o0;
                *(float2*)&out[i1] = o1;
            }
        }
    }
}

__global__ __launch_bounds__(512)
void mma_gemm(const uint8_t* __restrict__ As, const uint8_t* __restrict__ Wp,
              const float* __restrict__ bias, const float* res,
              float* out, uint8_t* out_split, int K, int do_relu) {
    gemm_core(As, Wp, bias, res, out, out_split, K, do_relu, blockIdx.x);
}

__global__ __launch_bounds__(512)
void qkv_gemm(const uint8_t* __restrict__ As, const uint8_t* __restrict__ WpBase,
              const float* __restrict__ bq, const float* __restrict__ bk,
              const float* __restrict__ bv,
              float* oq, float* ok, float* ov) {
    int mat = blockIdx.y;
    const uint8_t* Wp = WpBase + (size_t)(3 + mat) * WPACK_STRIDE;
    const float* bias = (mat == 0) ? bq : ((mat == 1) ? bk : bv);
    float* out = (mat == 0) ? oq : ((mat == 1) ? ok : ov);
    gemm_core(As, Wp, bias, nullptr, out, nullptr, 256, 0, blockIdx.x);
}

// ---------------------------------------------------------------------------
// SIMT fp32 adjmul writing split image directly.
// blockIdx.x = bt, blockIdx.y = 64-wide f chunk. 512 threads.
// ---------------------------------------------------------------------------
__global__ __launch_bounds__(512)
void adjmul_split(const float* __restrict__ h, const float* __restrict__ adj,
                  uint8_t* __restrict__ dst, int F_total) {
    extern __shared__ float smf[];
    float* adj_s = smf;            // 100*100
    float* h_s   = smf + 10000;    // 100*64
    const int bt = blockIdx.x;
    const int chunk = blockIdx.y;
    const int f0 = chunk * 64;
    const int ncK = F_total >> 6;
    const float* hp = h + (size_t)bt * Nz * F_total;

    {
        const float4* a4 = (const float4*)adj;
        float4* s4 = (float4*)adj_s;
        for (int i = threadIdx.x; i < 2500; i += 512) s4[i] = a4[i];
        for (int i = threadIdx.x; i < 1600; i += 512) {
            int row = i >> 4, c4 = i & 15;
            ((float4*)h_s)[i] = *(const float4*)&hp[(size_t)row * F_total + f0 + c4 * 4];
        }
    }
    __syncthreads();

    const int fq = threadIdx.x & 15;
    const int nl = threadIdx.x >> 4;
    const int n0 = nl * 4;
    if (n0 >= Nz) return;
    const float4* h4 = (const float4*)h_s;

    float4 a0 = make_float4(0.f, 0.f, 0.f, 0.f), a1 = a0, a2 = a0, a3 = a0;
    #pragma unroll 2
    for (int m = 0; m < Nz; m++) {
        float4 hv = h4[m * 16 + fq];
        float w0 = adj_s[(n0 + 0) * Nz + m];
        float w1 = adj_s[(n0 + 1) * Nz + m];
        float w2 = adj_s[(n0 + 2) * Nz + m];
        float w3 = adj_s[(n0 + 3) * Nz + m];
        a0.x += w0 * hv.x; a0.y += w0 * hv.y; a0.z += w0 * hv.z; a0.w += w0 * hv.w;
        a1.x += w1 * hv.x; a1.y += w1 * hv.y; a1.z += w1 * hv.z; a1.w += w1 * hv.w;
        a2.x += w2 * hv.x; a2.y += w2 * hv.y; a2.z += w2 * hv.z; a2.w += w2 * hv.w;
        a3.x += w3 * hv.x; a3.y += w3 * hv.y; a3.z += w3 * hv.z; a3.w += w3 * hv.w;
    }

    const int kc = fq >> 1;
    const int inner = (fq & 1) * 8;
    float4 vals[4] = {a0, a1, a2, a3};
    #pragma unroll
    for (int r = 0; r < 4; r++) {
        int mg = bt * Nz + n0 + r;
        int mtile = mg >> 7, row = mg & 127;
        uint8_t* block = dst + (size_t)(mtile * ncK + chunk) * 32768;
        uint32_t boff = (uint32_t)(row * 128 + ((kc ^ (row & 7)) << 4) + inner);
        uint32_t h0, l0, h1, l1;
        split_h2(vals[r].x, vals[r].y, h0, l0);
        split_h2(vals[r].z, vals[r].w, h1, l1);
        *(uint2*)(block + boff) = make_uint2(h0, h1);
        *(uint2*)(block + 16384 + boff) = make_uint2(l0, l1);
    }
}

// ---------------------------------------------------------------------------
// Temporal attention; output written as split image (feeds Wp GEMM).
// ---------------------------------------------------------------------------
#define QS 268

__global__ __launch_bounds__(512)
void attn_kernel(const float* __restrict__ q, const float* __restrict__ k,
                 const float* __restrict__ v, uint8_t* __restrict__ dst) {
    extern __shared__ float smf[];
    float* q_s = smf;
    float* k_s = q_s + Tz * QS;
    float* v_s = k_s + Tz * QS;
    float* p_s = v_s + Tz * QS;

    const int b = blockIdx.x / Nz;
    const int n = blockIdx.x % Nz;
    const size_t base = ((size_t)b * Tz * Nz + n) * Hz;
    const size_t tstride = (size_t)Nz * Hz;

    for (int i = threadIdx.x; i < Tz * Hz; i += blockDim.x) {
        int t = i >> 8; int hh = i & 255;
        q_s[t * QS + hh] = q[base + t * tstride + hh];
        k_s[t * QS + hh] = k[base + t * tstride + hh];
        v_s[t * QS + hh] = v[base + t * tstride + hh];
    }
    __syncthreads();

    if (threadIdx.x < Tz * Tz) {
        int t = threadIdx.x / Tz, s = threadIdx.x % Tz;
        const float4* q4 = (const float4*)(q_s + t * QS);
        const float4* k4 = (const float4*)(k_s + s * QS);
        float a0 = 0.f, a1 = 0.f;
        #pragma unroll 8
        for (int c = 0; c < 64; c += 2) {
            float4 qa = q4[c], ka = k4[c];
            float4 qb = q4[c + 1], kb = k4[c + 1];
            a0 += qa.x * ka.x + qa.y * ka.y + qa.z * ka.z + qa.w * ka.w;
            a1 += qb.x * kb.x + qb.y * kb.y + qb.z * kb.z + qb.w * kb.w;
        }
        p_s[t * 21 + s] = (a0 + a1) * 0.0625f;
    }
    __syncthreads();

    if (threadIdx.x < Tz) {
        int t = threadIdx.x;
        float mx = -1e30f;
        #pragma unroll
        for (int s = 0; s < Tz; s++) mx = fmaxf(mx, p_s[t * 21 + s]);
        float sum = 0.f;
        #pragma unroll
        for (int s = 0; s < Tz; s++) {
            float e = expf(p_s[t * 21 + s] - mx);
            p_s[t * 21 + s] = e; sum += e;
        }
        float inv = 1.f / sum;
        #pragma unroll
        for (int s = 0; s < Tz; s++) p_s[t * 21 + s] *= inv;
    }
    __syncthreads();

    // out = attn @ v, written as split image. Unit = (t, 8-wide h group).
    for (int u = threadIdx.x; u < Tz * 32; u += 512) {
        int t = u >> 5, hgrp = u & 31;
        float acc[8] = {};
        #pragma unroll
        for (int s = 0; s < Tz; s++) {
            float p = p_s[t * 21 + s];
            const float4* vv = (const float4*)(v_s + s * QS + hgrp * 8);
            float4 va = vv[0], vb = vv[1];
            acc[0] += p * va.x; acc[1] += p * va.y; acc[2] += p * va.z; acc[3] += p * va.w;
            acc[4] += p * vb.x; acc[5] += p * vb.y; acc[6] += p * vb.z; acc[7] += p * vb.w;
        }
        int mg = b * Tz * Nz + t * Nz + n;
        int mtile = mg >> 7, row = mg & 127;
        int chunk = hgrp >> 3, kc = hgrp & 7;
        uint8_t* block = dst + (size_t)(mtile * 4 + chunk) * 32768;
        uint32_t boff = (uint32_t)(row * 128 + ((kc ^ (row & 7)) << 4));
        uint32_t hi[4], lo[4];
        split_h2(acc[0], acc[1], hi[0], lo[0]);
        split_h2(acc[2], acc[3], hi[1], lo[1]);
        split_h2(acc[4], acc[5], hi[2], lo[2]);
        split_h2(acc[6], acc[7], hi[3], lo[3]);
        *(uint4*)(block + boff) = make_uint4(hi[0], hi[1], hi[2], hi[3]);
        *(uint4*)(block + 16384 + boff) = make_uint4(lo[0], lo[1], lo[2], lo[3]);
    }
}

// ---------------------------------------------------------------------------
// LayerNorm
// ---------------------------------------------------------------------------
__global__ __launch_bounds__(256)
void ln_kernel(const float* __restrict__ a, const float* __restrict__ gamma,
               const float* __restrict__ beta, float* __restrict__ out) {
    __shared__ float ss[8], qq[8];
    const size_t row = blockIdx.x;
    const int t = threadIdx.x;
    float x = a[row * 256 + t];
    float s = x, q = x * x;
    #pragma unroll
    for (int o = 16; o > 0; o >>= 1) {
        s += __shfl_xor_sync(0xffffffffu, s, o);
        q += __shfl_xor_sync(0xffffffffu, q, o);
    }
    int w = t >> 5, l = t & 31;
    if (l == 0) { ss[w] = s; qq[w] = q; }
    __syncthreads();
    float S = 0.f, Q = 0.f;
    #pragma unroll
    for (int i = 0; i < 8; i++) { S += ss[i]; Q += qq[i]; }
    float mu = S * (1.f / 256.f);
    float var = Q * (1.f / 256.f) - mu * mu;
    float r = rsqrtf(var + 1e-5f);
    out[row * 256 + t] = (x - mu) * r * gamma[t] + beta[t];
}

// ---------------------------------------------------------------------------
// launch
// ---------------------------------------------------------------------------
extern "C" void kernel_launch(void* const* d_in, const int* in_sizes, int n_in,
                              void* d_out, int out_size) {
    const float* x    = (const float*)d_in[0];
    const float* adj  = (const float*)d_in[1];
    const float* W0   = (const float*)d_in[2];
    const float* b0   = (const float*)d_in[3];
    const float* W1   = (const float*)d_in[4];
    const float* b1   = (const float*)d_in[5];
    const float* W2   = (const float*)d_in[6];
    const float* b2   = (const float*)d_in[7];
    const float* Wq   = (const float*)d_in[8];
    const float* bq   = (const float*)d_in[9];
    const float* Wk   = (const float*)d_in[10];
    const float* bk   = (const float*)d_in[11];
    const float* Wv   = (const float*)d_in[12];
    const float* bv   = (const float*)d_in[13];
    const float* Wp   = (const float*)d_in[14];
    const float* bp   = (const float*)d_in[15];
    const float* gamma = (const float*)d_in[16];
    const float* beta  = (const float*)d_in[17];
    float* out = (float*)d_out;

    float *ph, *pg, *pq, *pk, *pv;
    uint8_t *wp, *as1;
    cudaGetSymbolAddress((void**)&ph, g_h);
    cudaGetSymbolAddress((void**)&pg, g_g);
    cudaGetSymbolAddress((void**)&pq, g_q);
    cudaGetSymbolAddress((void**)&pk, g_k);
    cudaGetSymbolAddress((void**)&pv, g_v);
    cudaGetSymbolAddress((void**)&wp, g_wpack);
    cudaGetSymbolAddress((void**)&as1, g_asplit);
    uint8_t* as2 = (uint8_t*)pg;

    const int smem_adj  = (10000 + Nz * 64) * 4;         // 65.6 KB
    const int smem_attn = (3 * Tz * QS + Tz * 21) * 4;   // ~66 KB
    cudaFuncSetAttribute(adjmul_split, cudaFuncAttributeMaxDynamicSharedMemorySize, smem_adj);
    cudaFuncSetAttribute(attn_kernel,  cudaFuncAttributeMaxDynamicSharedMemorySize, smem_attn);
    cudaFuncSetAttribute(mma_gemm,     cudaFuncAttributeMaxDynamicSharedMemorySize, SMEM_GEMM);
    cudaFuncSetAttribute(qkv_gemm,     cudaFuncAttributeMaxDynamicSharedMemorySize, SMEM_GEMM);

    W7 ws;
    ws.w[0] = W0; ws.w[1] = W1; ws.w[2] = W2; ws.w[3] = Wq;
    ws.w[4] = Wk; ws.w[5] = Wv; ws.w[6] = Wp;
    pack_w_all<<<dim3(256, 7), 256>>>(ws, wp);

    const int BT = Bz * Tz;                 // 1280
    const int M = Bz * Tz * Nz;             // 128000
    const int GT = M / 128;                 // 1000 CTAs

    // GCN layer 0 (F=64 -> H=256)
    adjmul_split<<<dim3(BT, 1), 512, smem_adj>>>(x, adj, as1, Fz);
    mma_gemm<<<GT, 512, SMEM_GEMM>>>(as1, wp + 0 * WPACK_STRIDE, b0, nullptr, ph, nullptr, Fz, 1);
    // GCN layer 1 (residual)
    adjmul_split<<<dim3(BT, 4), 512, smem_adj>>>(ph, adj, as1, Hz);
    mma_gemm<<<GT, 512, SMEM_GEMM>>>(as1, wp + 1 * WPACK_STRIDE, b1, ph, ph, nullptr, Hz, 1);
    // GCN layer 2 (residual) -> split image directly (feeds QKV)
    adjmul_split<<<dim3(BT, 4), 512, smem_adj>>>(ph, adj, as1, Hz);
    mma_gemm<<<GT, 512, SMEM_GEMM>>>(as1, wp + 2 * WPACK_STRIDE, b2, ph, nullptr, as2, Hz, 1);
    // Q, K, V fused launch
    qkv_gemm<<<dim3(GT, 3), 512, SMEM_GEMM>>>(as2, wp, bq, bk, bv, pq, pk, pv);
    // attention -> split image (feeds Wp GEMM)
    attn_kernel<<<Bz * Nz, 512, smem_attn>>>(pq, pk, pv, as1);
    // output projection
    mma_gemm<<<GT, 512, SMEM_GEMM>>>(as1, wp + 6 * WPACK_STRIDE, bp, nullptr, pq, nullptr, Hz, 0);
    // layernorm
    ln_kernel<<<M, 256>>>(pq, gamma, beta, out);
}